// round 12
// baseline (speedup 1.0000x reference)
#include <cuda_runtime.h>
#include <cuda_bf16.h>
#include <math.h>
#include <stdint.h>

// ---------------- problem constants ----------------
#define BATCH   2
#define SEQ     8192
#define DMODEL  512
#define NH      8
#define DH      64
#define BHEADS  16
#define BNROWS  16384
#define QKVN    1536
#define HID     1365
#define HID2    2730
#define HID2P   2816
#define KFF2    1408
#define WSIZE   512

// ---------------- scratch buffers ----------------
__device__ __nv_bfloat16 g_h   [(size_t)BNROWS * DMODEL];
__device__ __nv_bfloat16 g_q   [(size_t)BHEADS * SEQ * DH];   // pre-scaled by 8*log2e
__device__ __nv_bfloat16 g_k   [(size_t)BHEADS * SEQ * DH];
__device__ __nv_bfloat16 g_v   [(size_t)BHEADS * SEQ * DH];
__device__ __nv_bfloat16 g_o   [(size_t)BNROWS * DMODEL];
__device__ float         g_x1  [(size_t)BNROWS * DMODEL];
__device__ __nv_bfloat16 g_gate[(size_t)BNROWS * KFF2];
__device__ __nv_bfloat16 g_WqkvT[(size_t)QKVN * DMODEL];
__device__ __nv_bfloat16 g_WoutT[(size_t)DMODEL * DMODEL];
__device__ __nv_bfloat16 g_W1iT [(size_t)HID2P * DMODEL];
__device__ __nv_bfloat16 g_W2T  [(size_t)DMODEL * KFF2];
__device__ float         g_b1i  [HID2P];

// ---------------- helpers ----------------
__device__ __forceinline__ float ex2f(float x) {
    float y;
    asm("ex2.approx.f32 %0, %1;" : "=f"(y) : "f"(x));
    return y;
}
__device__ __forceinline__ void mma_bf16(float c[4], const unsigned a[4], const unsigned b[2]) {
    asm volatile(
        "mma.sync.aligned.m16n8k16.row.col.f32.bf16.bf16.f32 "
        "{%0,%1,%2,%3}, {%4,%5,%6,%7}, {%8,%9}, {%0,%1,%2,%3};"
        : "+f"(c[0]), "+f"(c[1]), "+f"(c[2]), "+f"(c[3])
        : "r"(a[0]), "r"(a[1]), "r"(a[2]), "r"(a[3]), "r"(b[0]), "r"(b[1]));
}
__device__ __forceinline__ void ldsm_x4(unsigned r[4], uint32_t addr) {
    asm volatile("ldmatrix.sync.aligned.m8n8.x4.shared.b16 {%0,%1,%2,%3}, [%4];"
                 : "=r"(r[0]), "=r"(r[1]), "=r"(r[2]), "=r"(r[3]) : "r"(addr));
}
__device__ __forceinline__ void ldsm_x4_t(unsigned r[4], uint32_t addr) {
    asm volatile("ldmatrix.sync.aligned.m8n8.x4.trans.shared.b16 {%0,%1,%2,%3}, [%4];"
                 : "=r"(r[0]), "=r"(r[1]), "=r"(r[2]), "=r"(r[3]) : "r"(addr));
}
__device__ __forceinline__ unsigned packbf2(float lo, float hi) {
    unsigned d;
    asm("cvt.rn.bf16x2.f32 %0, %1, %2;" : "=r"(d) : "f"(hi), "f"(lo));
    return d;
}
__device__ __forceinline__ void cp16(const void* s, const void* g) {
    unsigned sa = (unsigned)__cvta_generic_to_shared(s);
    asm volatile("cp.async.cg.shared.global [%0], [%1], 16;" :: "r"(sa), "l"(g));
}
__device__ __forceinline__ void cp_commit() { asm volatile("cp.async.commit_group;"); }
template<int NN> __device__ __forceinline__ void cp_wait() {
    asm volatile("cp.async.wait_group %0;" :: "n"(NN));
}

// ---------------- weight prep ----------------
template<bool REMAP>
__global__ void transpose_bf16_k(const float* __restrict__ src, __nv_bfloat16* __restrict__ dst,
                                 int Ksrc, int Nsrc, int Kpad)
{
    __shared__ float t[32][33];
    int n0 = blockIdx.x * 32, k0 = blockIdx.y * 32;
    int x = threadIdx.x, y = threadIdx.y;
    #pragma unroll
    for (int i = 0; i < 32; i += 8) {
        int k = k0 + y + i, j = n0 + x;
        int c = REMAP ? ((j >> 1) + (j & 1) * HID) : j;
        int nlim = REMAP ? HID2 : Nsrc;
        t[y + i][x] = (k < Ksrc && j < nlim) ? src[(size_t)k * Nsrc + c] : 0.0f;
    }
    __syncthreads();
    #pragma unroll
    for (int i = 0; i < 32; i += 8) {
        int n = n0 + y + i, k = k0 + x;
        dst[(size_t)n * Kpad + k] = __float2bfloat16(t[x][y + i]);
    }
}
__global__ void b1i_kernel(const float* __restrict__ b1)
{
    int j = blockIdx.x * 256 + threadIdx.x;
    if (j < HID2P) g_b1i[j] = (j < HID2) ? b1[(j >> 1) + (j & 1) * HID] : 0.0f;
}

// ---------------- LayerNorm (emits bf16) ----------------
__global__ void ln_kernel(const float* __restrict__ x,
                          const float* __restrict__ gamma,
                          const float* __restrict__ beta,
                          __nv_bfloat16* __restrict__ out)
{
    int row = blockIdx.x;
    int tid = threadIdx.x;
    const float* xr = x + (size_t)row * DMODEL;
    float v0 = xr[tid];
    float v1 = xr[tid + 256];
    float s  = v0 + v1;
    float ss = v0 * v0 + v1 * v1;

    __shared__ float shs[8], shss[8];
    #pragma unroll
    for (int o = 16; o > 0; o >>= 1) {
        s  += __shfl_down_sync(0xffffffffu, s,  o);
        ss += __shfl_down_sync(0xffffffffu, ss, o);
    }
    if ((tid & 31) == 0) { shs[tid >> 5] = s; shss[tid >> 5] = ss; }
    __syncthreads();
    if (tid < 8) {
        s = shs[tid]; ss = shss[tid];
        #pragma unroll
        for (int o = 4; o > 0; o >>= 1) {
            s  += __shfl_down_sync(0xffu, s,  o);
            ss += __shfl_down_sync(0xffu, ss, o);
        }
        if (tid == 0) { shs[0] = s; shss[0] = ss; }
    }
    __syncthreads();
    float mean = shs[0]  * (1.0f / DMODEL);
    float var  = shss[0] * (1.0f / DMODEL) - mean * mean;
    float inv  = rsqrtf(var + 1e-5f);
    __nv_bfloat16* outr = out + (size_t)row * DMODEL;
    outr[tid]       = __float2bfloat16((v0 - mean) * inv * gamma[tid]       + beta[tid]);
    outr[tid + 256] = __float2bfloat16((v1 - mean) * inv * gamma[tid + 256] + beta[tid + 256]);
}

// ---------------- bf16 mma GEMM, 128x128 tile, 4-stage, ldmatrix fragments ----------------
// MODE: 0 f32 out; 1 +res; 2 +bias geglu->bf16 half-width (smem-bounced);
//       3 +bias+res; 5 fused qkv split + l2norm + rotary (smem-bounced)
#define GROWB 80                   // bytes per smem row (40 bf16)
#define GSTGB (128 * GROWB)        // bytes per stage (A or B)
#define GEMM_SMEM (8 * GSTGB)      // 4 stages x (A + B)

template<int MODE>
__global__ void __launch_bounds__(256, 2)
gemm_bf16(const __nv_bfloat16* __restrict__ A, const __nv_bfloat16* __restrict__ BT,
          const float* __restrict__ bias, const float* __restrict__ res,
          float* __restrict__ C, int K, int lda, int ldb, int ldc)
{
    extern __shared__ __nv_bfloat16 smem[];
    __nv_bfloat16 (*As)[40] = (__nv_bfloat16(*)[40])smem;
    __nv_bfloat16 (*Bs)[40] = (__nv_bfloat16(*)[40])(smem + 4 * 128 * 40);

    int tid  = threadIdx.x;
    int lane = tid & 31;
    int wid  = tid >> 5;
    int g  = lane >> 2;
    int tg = lane & 3;
    int wm = (wid & 1) * 64;
    int wn = (wid >> 1) * 32;
    int m0 = blockIdx.y * 128, n0 = blockIdx.x * 128;

    uint32_t smb   = (uint32_t)__cvta_generic_to_shared(smem);
    uint32_t aAddr = smb + (uint32_t)(wm + ((lane >> 3) & 1) * 8 + (lane & 7)) * GROWB
                         + (uint32_t)(lane >> 4) * 16;
    uint32_t bAddr = smb + 4 * GSTGB
                         + (uint32_t)(wn + ((lane >> 4) & 1) * 8 + (lane & 7)) * GROWB
                         + (uint32_t)((lane >> 3) & 1) * 16;

    float c[4][4][4];
    #pragma unroll
    for (int i = 0; i < 4; i++)
        #pragma unroll
        for (int j = 0; j < 4; j++)
            #pragma unroll
            for (int l = 0; l < 4; l++) c[i][j][l] = 0.0f;

    int T = K >> 5;

    auto stage = [&](int st, int k0) {
        #pragma unroll
        for (int i = 0; i < 2; i++) {
            int idx = i * 256 + tid;
            int row = idx >> 2, c8 = (idx & 3) * 8;
            cp16(&As[st * 128 + row][c8], A + (size_t)(m0 + row) * lda + k0 + c8);
            cp16(&Bs[st * 128 + row][c8], BT + (size_t)(n0 + row) * ldb + k0 + c8);
        }
        cp_commit();
    };

    stage(0, 0);
    if (T > 1) stage(1, 32);
    if (T > 2) stage(2, 64);

    for (int kt = 0; kt < T; kt++) {
        if (kt + 2 < T)      { cp_wait<2>(); }
        else if (kt + 1 < T) { cp_wait<1>(); }
        else                 { cp_wait<0>(); }
        __syncthreads();
        if (kt + 3 < T) stage((kt + 3) & 3, (kt + 3) * 32);

        uint32_t stOff = (uint32_t)(kt & 3) * GSTGB;
        #pragma unroll
        for (int ks = 0; ks < 2; ks++) {
            uint32_t kb = ks * 32;
            unsigned a[4][4], bq[2][4];
            #pragma unroll
            for (int mf = 0; mf < 4; mf++)
                ldsm_x4(a[mf], aAddr + stOff + mf * (16 * GROWB) + kb);
            #pragma unroll
            for (int nfp = 0; nfp < 2; nfp++)
                ldsm_x4(bq[nfp], bAddr + stOff + nfp * (16 * GROWB) + kb);
            #pragma unroll
            for (int mf = 0; mf < 4; mf++)
                #pragma unroll
                for (int nf = 0; nf < 4; nf++)
                    mma_bf16(c[mf][nf], a[mf], &bq[nf >> 1][(nf & 1) * 2]);
        }
    }

    if (MODE == 2 || MODE == 5) {
        __syncthreads();   // all warps done reading stage smem
        if (MODE == 2) {
            __nv_bfloat16* Cb = (__nv_bfloat16*)C;
            __nv_bfloat16 (*sm2)[72] = (__nv_bfloat16(*)[72])smem;
            #pragma unroll
            for (int mf = 0; mf < 4; mf++) {
                #pragma unroll
                for (int nf = 0; nf < 4; nf++) {
                    int lc = wn / 2 + nf * 4 + tg;
                    #pragma unroll
                    for (int half = 0; half < 2; half++) {
                        int lr = wm + mf * 16 + g + half * 8;
                        int col = n0 + wn + nf * 8 + 2 * tg;
                        float xa = c[mf][nf][half * 2]     + bias[col];
                        float yg = c[mf][nf][half * 2 + 1] + bias[col + 1];
                        float ge = 0.5f * yg * (1.0f + erff(yg * 0.70710678118654752f));
                        sm2[lr][lc] = __float2bfloat16(xa * ge);
                    }
                }
            }
            __syncthreads();
            #pragma unroll
            for (int it = 0; it < 4; it++) {
                int idx = it * 256 + tid;
                int lr = idx >> 3, ch = idx & 7;
                *(float4*)&Cb[(size_t)(m0 + lr) * ldc + (n0 >> 1) + ch * 8] =
                    *(const float4*)&sm2[lr][ch * 8];
            }
        } else {
            // MODE 5: fused qkv split + l2norm + scale + rotary xpos
            __nv_bfloat16 (*sm4)[136] = (__nv_bfloat16(*)[136])smem;
            #pragma unroll
            for (int mf = 0; mf < 4; mf++) {
                #pragma unroll
                for (int nf = 0; nf < 4; nf++) {
                    int lc = wn + nf * 8 + 2 * tg;
                    #pragma unroll
                    for (int half = 0; half < 2; half++) {
                        int lr = wm + mf * 16 + g + half * 8;
                        __nv_bfloat162 o2;
                        o2.x = __float2bfloat16(c[mf][nf][half * 2]);
                        o2.y = __float2bfloat16(c[mf][nf][half * 2 + 1]);
                        *(__nv_bfloat162*)&sm4[lr][lc] = o2;
                    }
                }
            }
            __syncthreads();

            int lr  = tid >> 1;
            int hh  = tid & 1;
            int row = m0 + lr;
            int b   = row >> 13;             // / SEQ
            int n   = row & (SEQ - 1);
            int sect = n0 >> 9;              // 0=q, 1=k, 2=v
            int h    = ((n0 & 511) >> 6) + hh;
            size_t obase = ((size_t)(b * NH + h) * SEQ + n) * DH;
            const __nv_bfloat16* src = &sm4[lr][hh * 64];

            if (sect == 2) {
                __nv_bfloat16* dst = g_v + obase;
                #pragma unroll
                for (int i = 0; i < 8; i++)
                    *(float4*)&dst[i * 8] = *(const float4*)&src[i * 8];
            } else {
                unsigned arr[32];
                #pragma unroll
                for (int i = 0; i < 32; i++)
                    arr[i] = *(const unsigned*)&src[i * 2];
                float sumsq = 0.0f;
                #pragma unroll
                for (int i = 0; i < 32; i++) {
                    __nv_bfloat162 t2 = *(__nv_bfloat162*)&arr[i];
                    float lo = __bfloat162float(t2.x);
                    float hi = __bfloat162float(t2.y);
                    sumsq = fmaf(lo, lo, sumsq);
                    sumsq = fmaf(hi, hi, sumsq);
                }
                float inv = 1.0f / fmaxf(sqrtf(sumsq), 1e-12f);
                const float* scale = (sect == 0) ? bias : res;
                const float QSC = 11.541560327111708f;   // 8*log2(e)
                float pw = ((float)n - (float)(SEQ / 2)) / (float)(WSIZE / 2);
                float o0a[32], o1a[32];
                #pragma unroll
                for (int d = 0; d < 32; d++) {
                    __nv_bfloat162 ta = *(__nv_bfloat162*)&arr[d >> 1];
                    __nv_bfloat162 tb = *(__nv_bfloat162*)&arr[16 + (d >> 1)];
                    float v0 = ((d & 1) ? __bfloat162float(ta.y) : __bfloat162float(ta.x))
                               * inv * scale[d];
                    float v1 = ((d & 1) ? __bfloat162float(tb.y) : __bfloat162float(tb.x))
                               * inv * scale[d + 32];
                    float invf = exp2f((float)d * (-13.287712379549449f / 32.0f));
                    float fr = (float)n * invf;
                    float cs = cosf(fr), sn = sinf(fr);
                    float sv = (2.0f * (float)d + 0.4f * 64.0f) / (1.4f * 64.0f);
                    float xs = exp2f(pw * log2f(sv));
                    float m = (sect == 0) ? (QSC * xs) : (1.0f / xs);
                    o0a[d] = (v0 * cs - v1 * sn) * m;
                    o1a[d] = (v1 * cs + v0 * sn) * m;
                }
                unsigned outp[32];
                #pragma unroll
                for (int j = 0; j < 16; j++) {
                    outp[j]      = packbf2(o0a[2 * j], o0a[2 * j + 1]);
                    outp[16 + j] = packbf2(o1a[2 * j], o1a[2 * j + 1]);
                }
                __nv_bfloat16* dst = ((sect == 0) ? g_q : g_k) + obase;
                #pragma unroll
                for (int i = 0; i < 8; i++) {
                    uint4 v4 = make_uint4(outp[4 * i], outp[4 * i + 1],
                                          outp[4 * i + 2], outp[4 * i + 3]);
                    *(uint4*)&dst[i * 8] = v4;
                }
            }
        }
        return;
    }

    #pragma unroll
    for (int mf = 0; mf < 4; mf++) {
        int r0 = m0 + wm + mf * 16 + g;
        #pragma unroll
        for (int nf = 0; nf < 4; nf++) {
            int col = n0 + wn + nf * 8 + 2 * tg;
            #pragma unroll
            for (int half = 0; half < 2; half++) {
                int r = r0 + half * 8;
                float cx = c[mf][nf][half * 2];
                float cy = c[mf][nf][half * 2 + 1];
                if (MODE == 0) {
                    *(float2*)&C[(size_t)r * ldc + col] = make_float2(cx, cy);
                } else if (MODE == 1) {
                    float2 rr = *(const float2*)&res[(size_t)r * ldc + col];
                    *(float2*)&C[(size_t)r * ldc + col] =
                        make_float2(cx + rr.x, cy + rr.y);
                } else {
                    float2 rr = *(const float2*)&res[(size_t)r * ldc + col];
                    *(float2*)&C[(size_t)r * ldc + col] =
                        make_float2(cx + bias[col] + rr.x,
                                    cy + bias[col + 1] + rr.y);
                }
            }
        }
    }
}

// ---------------- local windowed attention: QK + PV bf16 mma, 3-buffer ----------------
#define AKROW 144                       // bytes per K/V smem row (72 bf16)
#define ABUF  (64 * AKROW)              // bytes per buffer per matrix
#define ATTN_SMEM (6 * ABUF)            // 3 buffers x (K + V)

__global__ void __launch_bounds__(256) attn_kernel()
{
    extern __shared__ char asmem[];
    __nv_bfloat16 (*Ks)[72] = (__nv_bfloat16(*)[72])asmem;
    __nv_bfloat16 (*Vs)[72] = (__nv_bfloat16(*)[72])(asmem + 3 * ABUF);

    const int tid  = threadIdx.x;
    const int lane = tid & 31;
    const int wq   = tid >> 5;
    const int g    = lane >> 2;
    const int tg   = lane & 3;
    const int qb   = blockIdx.x;
    const int bh   = blockIdx.y;
    const int t0   = qb * 128;
    const int w    = t0 >> 9;
    const int rstart = (w > 0) ? 0 : ((512 - (t0 & 511)) >> 6);

    uint32_t vsb   = (uint32_t)__cvta_generic_to_shared(&Vs[0][0]);
    uint32_t vAddr = vsb + (uint32_t)(((lane >> 3) & 1) * 8 + (lane & 7)) * AKROW
                         + (uint32_t)(lane >> 4) * 16;

    unsigned qf[4][4];
    {
        const __nv_bfloat16* qb0 = g_q + ((size_t)bh * SEQ + t0 + wq * 16) * DH;
        #pragma unroll
        for (int kc = 0; kc < 4; kc++) {
            qf[kc][0] = *(const unsigned*)&qb0[(size_t)g * DH + kc * 16 + 2 * tg];
            qf[kc][1] = *(const unsigned*)&qb0[(size_t)(g + 8) * DH + kc * 16 + 2 * tg];
            qf[kc][2] = *(const unsigned*)&qb0[(size_t)g * DH + kc * 16 + 2 * tg + 8];
            qf[kc][3] = *(const unsigned*)&qb0[(size_t)(g + 8) * DH + kc * 16 + 2 * tg + 8];
        }
    }

    float o[8][4];
    #pragma unroll
    for (int i = 0; i < 8; i++)
        #pragma unroll
        for (int j = 0; j < 4; j++) o[i][j] = 0.0f;
    float d0 = 0.0f, d1 = 0.0f;

    const __nv_bfloat16* kbase = g_k + (size_t)bh * SEQ * DH;
    const __nv_bfloat16* vbase = g_v + (size_t)bh * SEQ * DH;

    auto stage = [&](int buf, int r) {
        int kg0 = t0 - 512 + 64 * r;
        #pragma unroll
        for (int i = 0; i < 2; i++) {
            int idx = i * 256 + tid;
            int kk = idx >> 3, d8 = (idx & 7) * 8;
            cp16(&Ks[buf * 64 + kk][d8], kbase + (size_t)(kg0 + kk) * DH + d8);
            cp16(&Vs[buf * 64 + kk][d8], vbase + (size_t)(kg0 + kk) * DH + d8);
        }
        cp_commit();
    };

    stage(0, rstart);
    if (rstart + 1 <= 9) stage(1, rstart + 1);

    const int q0r = wq * 16 + g;

    for (int r = rstart; r <= 9; r++) {
        int i  = r - rstart;
        int bi = i % 3;
        if (r < 9) { cp_wait<1>(); } else { cp_wait<0>(); }
        __syncthreads();
        if (r + 2 <= 9) stage((i + 2) % 3, r + 2);

        float s[8][4];
        #pragma unroll
        for (int ii = 0; ii < 8; ii++)
            #pragma unroll
            for (int j = 0; j < 4; j++) s[ii][j] = 0.0f;

        #pragma unroll
        for (int kc = 0; kc < 4; kc++) {
            #pragma unroll
            for (int nf = 0; nf < 8; nf++) {
                unsigned b[2];
                const __nv_bfloat16* kr = &Ks[bi * 64 + nf * 8 + g][kc * 16 + 2 * tg];
                b[0] = *(const unsigned*)kr;
                b[1] = *(const unsigned*)(kr + 8);
                mma_bf16(s[nf], qf[kc], b);
            }
        }

        float p[8][4];
        #pragma unroll
        for (int nf = 0; nf < 8; nf++) {
            int j0  = nf * 8 + 2 * tg;
            int jr0 = 64 * r - 512 + j0;
            int jr1 = jr0 + 1;
            bool ok0 = (jr0 <= q0r)     && (jr0 >= q0r - 512);
            bool ok1 = (jr1 <= q0r)     && (jr1 >= q0r - 512);
            bool ok2 = (jr0 <= q0r + 8) && (jr0 >= q0r - 504);
            bool ok3 = (jr1 <= q0r + 8) && (jr1 >= q0r - 504);
            p[nf][0] = ok0 ? ex2f(s[nf][0]) : 0.0f;
            p[nf][1] = ok1 ? ex2f(s[nf][1]) : 0.0f;
            p[nf][2] = ok2 ? ex2f(s[nf][2]) : 0.0f;
            p[nf][3] = ok3 ? ex2f(s[nf][3]) : 0.0f;
            d0 += p[nf][0] + p[nf][1];
            d1 += p[nf][2] + p[nf][3];
        }

        uint32_t vbufAddr = vAddr + (uint32_t)bi * ABUF;
        #pragma unroll
        for (int kc = 0; kc < 4; kc++) {
            unsigned a[4];
            a[0] = packbf2(p[2 * kc][0],     p[2 * kc][1]);
            a[1] = packbf2(p[2 * kc][2],     p[2 * kc][3]);
            a[2] = packbf2(p[2 * kc + 1][0], p[2 * kc + 1][1]);
            a[3] = packbf2(p[2 * kc + 1][2], p[2 * kc + 1][3]);
            #pragma unroll
            for (int nfp = 0; nfp < 4; nfp++) {
                unsigned bv[4];
                ldsm_x4_t(bv, vbufAddr + (uint32_t)kc * (16 * AKROW) + (uint32_t)nfp * 32);
                mma_bf16(o[2 * nfp],     a, &bv[0]);
                mma_bf16(o[2 * nfp + 1], a, &bv[2]);
            }
        }
    }

    d0 += __shfl_xor_sync(0xffffffffu, d0, 1);
    d0 += __shfl_xor_sync(0xffffffffu, d0, 2);
    d1 += __shfl_xor_sync(0xffffffffu, d1, 1);
    d1 += __shfl_xor_sync(0xffffffffu, d1, 2);
    float i0 = 1.0f / d0, i1 = 1.0f / d1;

    int b = bh >> 3, h = bh & 7;
    int row0 = t0 + wq * 16 + g;
    __nv_bfloat16* ob = g_o + (size_t)b * SEQ * DMODEL + h * DH;
    #pragma unroll
    for (int nf = 0; nf < 8; nf++) {
        int col = nf * 8 + 2 * tg;
        __nv_bfloat162 lo, hi;
        lo.x = __float2bfloat16(o[nf][0] * i0);
        lo.y = __float2bfloat16(o[nf][1] * i0);
        hi.x = __float2bfloat16(o[nf][2] * i1);
        hi.y = __float2bfloat16(o[nf][3] * i1);
        *(__nv_bfloat162*)&ob[(size_t)row0 * DMODEL + col]       = lo;
        *(__nv_bfloat162*)&ob[(size_t)(row0 + 8) * DMODEL + col] = hi;
    }
}

// ---------------- launch ----------------
extern "C" void kernel_launch(void* const* d_in, const int* in_sizes, int n_in,
                              void* d_out, int out_size)
{
    const float* x     = (const float*)d_in[0];
    const float* ln1g  = (const float*)d_in[1];
    const float* ln1b  = (const float*)d_in[2];
    const float* Wqkv  = (const float*)d_in[3];
    const float* qsc   = (const float*)d_in[4];
    const float* ksc   = (const float*)d_in[5];
    const float* Wout  = (const float*)d_in[6];
    const float* ln2g  = (const float*)d_in[7];
    const float* ln2b  = (const float*)d_in[8];
    const float* W1    = (const float*)d_in[9];
    const float* b1    = (const float*)d_in[10];
    const float* W2    = (const float*)d_in[11];
    const float* b2    = (const float*)d_in[12];
    float* out = (float*)d_out;

    __nv_bfloat16 *ph, *po, *pg, *pWqkvT, *pWoutT, *pW1iT, *pW2T;
    float *px1, *pb1i;
    cudaGetSymbolAddress((void**)&ph,     g_h);
    cudaGetSymbolAddress((void**)&po,     g_o);
    cudaGetSymbolAddress((void**)&px1,    g_x1);
    cudaGetSymbolAddress((void**)&pg,     g_gate);
    cudaGetSymbolAddress((void**)&pWqkvT, g_WqkvT);
    cudaGetSymbolAddress((void**)&pWoutT, g_WoutT);
    cudaGetSymbolAddress((void**)&pW1iT,  g_W1iT);
    cudaGetSymbolAddress((void**)&pW2T,   g_W2T);
    cudaGetSymbolAddress((void**)&pb1i,   g_b1i);

    cudaFuncSetAttribute(gemm_bf16<0>, cudaFuncAttributeMaxDynamicSharedMemorySize, GEMM_SMEM);
    cudaFuncSetAttribute(gemm_bf16<1>, cudaFuncAttributeMaxDynamicSharedMemorySize, GEMM_SMEM);
    cudaFuncSetAttribute(gemm_bf16<2>, cudaFuncAttributeMaxDynamicSharedMemorySize, GEMM_SMEM);
    cudaFuncSetAttribute(gemm_bf16<3>, cudaFuncAttributeMaxDynamicSharedMemorySize, GEMM_SMEM);
    cudaFuncSetAttribute(gemm_bf16<5>, cudaFuncAttributeMaxDynamicSharedMemorySize, GEMM_SMEM);
    cudaFuncSetAttribute(attn_kernel,  cudaFuncAttributeMaxDynamicSharedMemorySize, ATTN_SMEM);

    // 0) weight prep
    {
        dim3 blk(32, 8);
        transpose_bf16_k<false><<<dim3(QKVN / 32, DMODEL / 32), blk>>>(
            Wqkv, pWqkvT, DMODEL, QKVN, DMODEL);
        transpose_bf16_k<false><<<dim3(DMODEL / 32, DMODEL / 32), blk>>>(
            Wout, pWoutT, DMODEL, DMODEL, DMODEL);
        transpose_bf16_k<true><<<dim3(HID2P / 32, DMODEL / 32), blk>>>(
            W1, pW1iT, DMODEL, HID2, DMODEL);
        transpose_bf16_k<false><<<dim3(DMODEL / 32, KFF2 / 32), blk>>>(
            W2, pW2T, HID, DMODEL, KFF2);
        b1i_kernel<<<(HID2P + 255) / 256, 256>>>(b1);
    }

    // 1) LN1 -> h (bf16)
    ln_kernel<<<BNROWS, 256>>>(x, ln1g, ln1b, ph);
    // 2) QKV GEMM + fused split/l2norm/rotary -> g_q, g_k, g_v
    gemm_bf16<5><<<dim3(QKVN / 128, BNROWS / 128), 256, GEMM_SMEM>>>(
        ph, pWqkvT, qsc, ksc, nullptr, DMODEL, DMODEL, DMODEL, 0);
    // 3) local attention -> o (bf16)
    attn_kernel<<<dim3(SEQ / 128, BHEADS), 256, ATTN_SMEM>>>();
    // 4) out projection + residual -> x1 (fp32)
    gemm_bf16<1><<<dim3(DMODEL / 128, BNROWS / 128), 256, GEMM_SMEM>>>(
        po, pWoutT, nullptr, x, px1, DMODEL, DMODEL, DMODEL, DMODEL);
    // 5) LN2 -> h (bf16)
    ln_kernel<<<BNROWS, 256>>>(px1, ln2g, ln2b, ph);
    // 6) FF1 + fused geglu -> gate (bf16, bounced stores)
    gemm_bf16<2><<<dim3(HID2P / 128, BNROWS / 128), 256, GEMM_SMEM>>>(
        ph, pW1iT, pb1i, nullptr, (float*)pg, DMODEL, DMODEL, DMODEL, KFF2);
    // 7) FF2 + b2 + residual -> out
    gemm_bf16<3><<<dim3(DMODEL / 128, BNROWS / 128), 256, GEMM_SMEM>>>(
        pg, pW2T, b2, px1, out, KFF2, KFF2, KFF2, DMODEL);
}

// round 13
// speedup vs baseline: 1.0427x; 1.0427x over previous
#include <cuda_runtime.h>
#include <cuda_bf16.h>
#include <math.h>
#include <stdint.h>

// ---------------- problem constants ----------------
#define BATCH   2
#define SEQ     8192
#define DMODEL  512
#define NH      8
#define DH      64
#define BHEADS  16
#define BNROWS  16384
#define QKVN    1536
#define HID     1365
#define HID2    2730
#define HID2P   2816
#define KFF2    1408
#define WSIZE   512

// ---------------- scratch buffers ----------------
__device__ __nv_bfloat16 g_h   [(size_t)BNROWS * DMODEL];
__device__ __nv_bfloat16 g_q   [(size_t)BHEADS * SEQ * DH];   // pre-scaled by 8*log2e
__device__ __nv_bfloat16 g_k   [(size_t)BHEADS * SEQ * DH];
__device__ __nv_bfloat16 g_v   [(size_t)BHEADS * SEQ * DH];
__device__ __nv_bfloat16 g_o   [(size_t)BNROWS * DMODEL];
__device__ float         g_x1  [(size_t)BNROWS * DMODEL];
__device__ __nv_bfloat16 g_gate[(size_t)BNROWS * KFF2];
__device__ __nv_bfloat16 g_WqkvT[(size_t)QKVN * DMODEL];
__device__ __nv_bfloat16 g_WoutT[(size_t)DMODEL * DMODEL];
__device__ __nv_bfloat16 g_W1iT [(size_t)HID2P * DMODEL];
__device__ __nv_bfloat16 g_W2T  [(size_t)DMODEL * KFF2];
__device__ float         g_b1i  [HID2P];
__device__ float4        g_rot  [(size_t)32 * SEQ];   // [d][n]: cos, sin, QSC*xs, 1/xs

// ---------------- helpers ----------------
__device__ __forceinline__ float ex2f(float x) {
    float y;
    asm("ex2.approx.f32 %0, %1;" : "=f"(y) : "f"(x));
    return y;
}
__device__ __forceinline__ void mma_bf16(float c[4], const unsigned a[4], const unsigned b[2]) {
    asm volatile(
        "mma.sync.aligned.m16n8k16.row.col.f32.bf16.bf16.f32 "
        "{%0,%1,%2,%3}, {%4,%5,%6,%7}, {%8,%9}, {%0,%1,%2,%3};"
        : "+f"(c[0]), "+f"(c[1]), "+f"(c[2]), "+f"(c[3])
        : "r"(a[0]), "r"(a[1]), "r"(a[2]), "r"(a[3]), "r"(b[0]), "r"(b[1]));
}
__device__ __forceinline__ void ldsm_x4(unsigned r[4], uint32_t addr) {
    asm volatile("ldmatrix.sync.aligned.m8n8.x4.shared.b16 {%0,%1,%2,%3}, [%4];"
                 : "=r"(r[0]), "=r"(r[1]), "=r"(r[2]), "=r"(r[3]) : "r"(addr));
}
__device__ __forceinline__ void ldsm_x4_t(unsigned r[4], uint32_t addr) {
    asm volatile("ldmatrix.sync.aligned.m8n8.x4.trans.shared.b16 {%0,%1,%2,%3}, [%4];"
                 : "=r"(r[0]), "=r"(r[1]), "=r"(r[2]), "=r"(r[3]) : "r"(addr));
}
__device__ __forceinline__ unsigned packbf2(float lo, float hi) {
    unsigned d;
    asm("cvt.rn.bf16x2.f32 %0, %1, %2;" : "=r"(d) : "f"(hi), "f"(lo));
    return d;
}
__device__ __forceinline__ void cp16(const void* s, const void* g) {
    unsigned sa = (unsigned)__cvta_generic_to_shared(s);
    asm volatile("cp.async.cg.shared.global [%0], [%1], 16;" :: "r"(sa), "l"(g));
}
__device__ __forceinline__ void cp_commit() { asm volatile("cp.async.commit_group;"); }
template<int NN> __device__ __forceinline__ void cp_wait() {
    asm volatile("cp.async.wait_group %0;" :: "n"(NN));
}

// ---------------- weight prep ----------------
template<bool REMAP>
__global__ void transpose_bf16_k(const float* __restrict__ src, __nv_bfloat16* __restrict__ dst,
                                 int Ksrc, int Nsrc, int Kpad)
{
    __shared__ float t[32][33];
    int n0 = blockIdx.x * 32, k0 = blockIdx.y * 32;
    int x = threadIdx.x, y = threadIdx.y;
    #pragma unroll
    for (int i = 0; i < 32; i += 8) {
        int k = k0 + y + i, j = n0 + x;
        int c = REMAP ? ((j >> 1) + (j & 1) * HID) : j;
        int nlim = REMAP ? HID2 : Nsrc;
        t[y + i][x] = (k < Ksrc && j < nlim) ? src[(size_t)k * Nsrc + c] : 0.0f;
    }
    __syncthreads();
    #pragma unroll
    for (int i = 0; i < 32; i += 8) {
        int n = n0 + y + i, k = k0 + x;
        dst[(size_t)n * Kpad + k] = __float2bfloat16(t[x][y + i]);
    }
}
__global__ void b1i_kernel(const float* __restrict__ b1)
{
    int j = blockIdx.x * 256 + threadIdx.x;
    if (j < HID2P) g_b1i[j] = (j < HID2) ? b1[(j >> 1) + (j & 1) * HID] : 0.0f;
}
// rotary trig table: [d][n]
__global__ void rot_table_kernel()
{
    int idx = blockIdx.x * 256 + threadIdx.x;   // 32*SEQ entries
    int d = idx >> 13;
    int n = idx & (SEQ - 1);
    float invf = exp2f((float)d * (-13.287712379549449f / 32.0f));
    float fr = (float)n * invf;
    float cs = cosf(fr), sn = sinf(fr);
    float sv = (2.0f * (float)d + 0.4f * 64.0f) / (1.4f * 64.0f);
    float pw = ((float)n - (float)(SEQ / 2)) / (float)(WSIZE / 2);
    float xs = exp2f(pw * log2f(sv));
    g_rot[idx] = make_float4(cs, sn, 11.541560327111708f * xs, 1.0f / xs);
}

// ---------------- LayerNorm (emits bf16) ----------------
__global__ void ln_kernel(const float* __restrict__ x,
                          const float* __restrict__ gamma,
                          const float* __restrict__ beta,
                          __nv_bfloat16* __restrict__ out)
{
    int row = blockIdx.x;
    int tid = threadIdx.x;
    const float* xr = x + (size_t)row * DMODEL;
    float v0 = xr[tid];
    float v1 = xr[tid + 256];
    float s  = v0 + v1;
    float ss = v0 * v0 + v1 * v1;

    __shared__ float shs[8], shss[8];
    #pragma unroll
    for (int o = 16; o > 0; o >>= 1) {
        s  += __shfl_down_sync(0xffffffffu, s,  o);
        ss += __shfl_down_sync(0xffffffffu, ss, o);
    }
    if ((tid & 31) == 0) { shs[tid >> 5] = s; shss[tid >> 5] = ss; }
    __syncthreads();
    if (tid < 8) {
        s = shs[tid]; ss = shss[tid];
        #pragma unroll
        for (int o = 4; o > 0; o >>= 1) {
            s  += __shfl_down_sync(0xffu, s,  o);
            ss += __shfl_down_sync(0xffu, ss, o);
        }
        if (tid == 0) { shs[0] = s; shss[0] = ss; }
    }
    __syncthreads();
    float mean = shs[0]  * (1.0f / DMODEL);
    float var  = shss[0] * (1.0f / DMODEL) - mean * mean;
    float inv  = rsqrtf(var + 1e-5f);
    __nv_bfloat16* outr = out + (size_t)row * DMODEL;
    outr[tid]       = __float2bfloat16((v0 - mean) * inv * gamma[tid]       + beta[tid]);
    outr[tid + 256] = __float2bfloat16((v1 - mean) * inv * gamma[tid + 256] + beta[tid + 256]);
}

// ---------------- bf16 mma GEMM, 128x128 tile, 4-stage, ldmatrix fragments ----------------
// MODE: 0 f32 out; 1 +res; 2 +bias geglu->bf16 half-width (smem-bounced);
//       3 +bias+res; 5 fused qkv split + l2norm + rotary via table (smem-bounced)
#define GROWB 80                   // bytes per smem row (40 bf16)
#define GSTGB (128 * GROWB)        // bytes per stage (A or B)
#define GEMM_SMEM (8 * GSTGB)      // 4 stages x (A + B)

template<int MODE>
__global__ void __launch_bounds__(256, 2)
gemm_bf16(const __nv_bfloat16* __restrict__ A, const __nv_bfloat16* __restrict__ BT,
          const float* __restrict__ bias, const float* __restrict__ res,
          float* __restrict__ C, int K, int lda, int ldb, int ldc)
{
    extern __shared__ __nv_bfloat16 smem[];
    __nv_bfloat16 (*As)[40] = (__nv_bfloat16(*)[40])smem;
    __nv_bfloat16 (*Bs)[40] = (__nv_bfloat16(*)[40])(smem + 4 * 128 * 40);

    int tid  = threadIdx.x;
    int lane = tid & 31;
    int wid  = tid >> 5;
    int g  = lane >> 2;
    int tg = lane & 3;
    int wm = (wid & 1) * 64;
    int wn = (wid >> 1) * 32;
    int m0 = blockIdx.y * 128, n0 = blockIdx.x * 128;

    uint32_t smb   = (uint32_t)__cvta_generic_to_shared(smem);
    uint32_t aAddr = smb + (uint32_t)(wm + ((lane >> 3) & 1) * 8 + (lane & 7)) * GROWB
                         + (uint32_t)(lane >> 4) * 16;
    uint32_t bAddr = smb + 4 * GSTGB
                         + (uint32_t)(wn + ((lane >> 4) & 1) * 8 + (lane & 7)) * GROWB
                         + (uint32_t)((lane >> 3) & 1) * 16;

    float c[4][4][4];
    #pragma unroll
    for (int i = 0; i < 4; i++)
        #pragma unroll
        for (int j = 0; j < 4; j++)
            #pragma unroll
            for (int l = 0; l < 4; l++) c[i][j][l] = 0.0f;

    int T = K >> 5;

    auto stage = [&](int st, int k0) {
        #pragma unroll
        for (int i = 0; i < 2; i++) {
            int idx = i * 256 + tid;
            int row = idx >> 2, c8 = (idx & 3) * 8;
            cp16(&As[st * 128 + row][c8], A + (size_t)(m0 + row) * lda + k0 + c8);
            cp16(&Bs[st * 128 + row][c8], BT + (size_t)(n0 + row) * ldb + k0 + c8);
        }
        cp_commit();
    };

    stage(0, 0);
    if (T > 1) stage(1, 32);
    if (T > 2) stage(2, 64);

    for (int kt = 0; kt < T; kt++) {
        if (kt + 2 < T)      { cp_wait<2>(); }
        else if (kt + 1 < T) { cp_wait<1>(); }
        else                 { cp_wait<0>(); }
        __syncthreads();
        if (kt + 3 < T) stage((kt + 3) & 3, (kt + 3) * 32);

        uint32_t stOff = (uint32_t)(kt & 3) * GSTGB;
        #pragma unroll
        for (int ks = 0; ks < 2; ks++) {
            uint32_t kb = ks * 32;
            unsigned a[4][4], bq[2][4];
            #pragma unroll
            for (int mf = 0; mf < 4; mf++)
                ldsm_x4(a[mf], aAddr + stOff + mf * (16 * GROWB) + kb);
            #pragma unroll
            for (int nfp = 0; nfp < 2; nfp++)
                ldsm_x4(bq[nfp], bAddr + stOff + nfp * (16 * GROWB) + kb);
            #pragma unroll
            for (int mf = 0; mf < 4; mf++)
                #pragma unroll
                for (int nf = 0; nf < 4; nf++)
                    mma_bf16(c[mf][nf], a[mf], &bq[nf >> 1][(nf & 1) * 2]);
        }
    }

    if (MODE == 2 || MODE == 5) {
        __syncthreads();   // all warps done reading stage smem
        if (MODE == 2) {
            __nv_bfloat16* Cb = (__nv_bfloat16*)C;
            __nv_bfloat16 (*sm2)[72] = (__nv_bfloat16(*)[72])smem;
            #pragma unroll
            for (int mf = 0; mf < 4; mf++) {
                #pragma unroll
                for (int nf = 0; nf < 4; nf++) {
                    int lc = wn / 2 + nf * 4 + tg;
                    #pragma unroll
                    for (int half = 0; half < 2; half++) {
                        int lr = wm + mf * 16 + g + half * 8;
                        int col = n0 + wn + nf * 8 + 2 * tg;
                        float xa = c[mf][nf][half * 2]     + bias[col];
                        float yg = c[mf][nf][half * 2 + 1] + bias[col + 1];
                        float ge = 0.5f * yg * (1.0f + erff(yg * 0.70710678118654752f));
                        sm2[lr][lc] = __float2bfloat16(xa * ge);
                    }
                }
            }
            __syncthreads();
            #pragma unroll
            for (int it = 0; it < 4; it++) {
                int idx = it * 256 + tid;
                int lr = idx >> 3, ch = idx & 7;
                *(float4*)&Cb[(size_t)(m0 + lr) * ldc + (n0 >> 1) + ch * 8] =
                    *(const float4*)&sm2[lr][ch * 8];
            }
        } else {
            // MODE 5: fused qkv split + l2norm + scale + rotary (table-driven)
            __nv_bfloat16 (*sm4)[136] = (__nv_bfloat16(*)[136])smem;
            #pragma unroll
            for (int mf = 0; mf < 4; mf++) {
                #pragma unroll
                for (int nf = 0; nf < 4; nf++) {
                    int lc = wn + nf * 8 + 2 * tg;
                    #pragma unroll
                    for (int half = 0; half < 2; half++) {
                        int lr = wm + mf * 16 + g + half * 8;
                        __nv_bfloat162 o2;
                        o2.x = __float2bfloat16(c[mf][nf][half * 2]);
                        o2.y = __float2bfloat16(c[mf][nf][half * 2 + 1]);
                        *(__nv_bfloat162*)&sm4[lr][lc] = o2;
                    }
                }
            }
            __syncthreads();

            int lr  = tid >> 1;
            int hh  = tid & 1;
            int row = m0 + lr;
            int b   = row >> 13;             // / SEQ
            int n   = row & (SEQ - 1);
            int sect = n0 >> 9;              // 0=q, 1=k, 2=v
            int h    = ((n0 & 511) >> 6) + hh;
            size_t obase = ((size_t)(b * NH + h) * SEQ + n) * DH;
            const __nv_bfloat16* src = &sm4[lr][hh * 64];

            if (sect == 2) {
                __nv_bfloat16* dst = g_v + obase;
                #pragma unroll
                for (int i = 0; i < 8; i++)
                    *(float4*)&dst[i * 8] = *(const float4*)&src[i * 8];
            } else {
                // pass 1: sum of squares over all 64 dims
                float sumsq = 0.0f;
                #pragma unroll
                for (int i = 0; i < 8; i++) {
                    uint4 v4 = *(const uint4*)&src[i * 8];
                    #pragma unroll
                    for (int j = 0; j < 4; j++) {
                        unsigned u = (&v4.x)[j];
                        __nv_bfloat162 t2 = *(__nv_bfloat162*)&u;
                        float lo = __bfloat162float(t2.x);
                        float hi = __bfloat162float(t2.y);
                        sumsq = fmaf(lo, lo, sumsq);
                        sumsq = fmaf(hi, hi, sumsq);
                    }
                }
                float inv = 1.0f / fmaxf(sqrtf(sumsq), 1e-12f);
                const float* scale = (sect == 0) ? bias : res;
                __nv_bfloat16* dst = ((sect == 0) ? g_q : g_k) + obase;

                // pass 2: rotate in 8-dim chunks, coalesced table reads
                #pragma unroll
                for (int i = 0; i < 4; i++) {
                    unsigned lo4[4], hi4[4];
                    #pragma unroll
                    for (int j = 0; j < 4; j++) {
                        int d0 = 8 * i + 2 * j;
                        __nv_bfloat162 ta = *(const __nv_bfloat162*)&src[d0];
                        __nv_bfloat162 tb = *(const __nv_bfloat162*)&src[d0 + 32];
                        float4 r0 = g_rot[(size_t)d0 * SEQ + n];
                        float4 r1 = g_rot[(size_t)(d0 + 1) * SEQ + n];
                        float va0 = __bfloat162float(ta.x) * inv * scale[d0];
                        float va1 = __bfloat162float(ta.y) * inv * scale[d0 + 1];
                        float vb0 = __bfloat162float(tb.x) * inv * scale[d0 + 32];
                        float vb1 = __bfloat162float(tb.y) * inv * scale[d0 + 33];
                        float m0v = (sect == 0) ? r0.z : r0.w;
                        float m1v = (sect == 0) ? r1.z : r1.w;
                        float o00 = (va0 * r0.x - vb0 * r0.y) * m0v;
                        float o01 = (va1 * r1.x - vb1 * r1.y) * m1v;
                        float o10 = (vb0 * r0.x + va0 * r0.y) * m0v;
                        float o11 = (vb1 * r1.x + va1 * r1.y) * m1v;
                        lo4[j] = packbf2(o00, o01);
                        hi4[j] = packbf2(o10, o11);
                    }
                    *(uint4*)&dst[8 * i]      = make_uint4(lo4[0], lo4[1], lo4[2], lo4[3]);
                    *(uint4*)&dst[32 + 8 * i] = make_uint4(hi4[0], hi4[1], hi4[2], hi4[3]);
                }
            }
        }
        return;
    }

    #pragma unroll
    for (int mf = 0; mf < 4; mf++) {
        int r0 = m0 + wm + mf * 16 + g;
        #pragma unroll
        for (int nf = 0; nf < 4; nf++) {
            int col = n0 + wn + nf * 8 + 2 * tg;
            #pragma unroll
            for (int half = 0; half < 2; half++) {
                int r = r0 + half * 8;
                float cx = c[mf][nf][half * 2];
                float cy = c[mf][nf][half * 2 + 1];
                if (MODE == 0) {
                    *(float2*)&C[(size_t)r * ldc + col] = make_float2(cx, cy);
                } else if (MODE == 1) {
                    float2 rr = *(const float2*)&res[(size_t)r * ldc + col];
                    *(float2*)&C[(size_t)r * ldc + col] =
                        make_float2(cx + rr.x, cy + rr.y);
                } else {
                    float2 rr = *(const float2*)&res[(size_t)r * ldc + col];
                    *(float2*)&C[(size_t)r * ldc + col] =
                        make_float2(cx + bias[col] + rr.x,
                                    cy + bias[col + 1] + rr.y);
                }
            }
        }
    }
}

// ---------------- local windowed attention: QK + PV bf16 mma, 3-buffer ----------------
#define AKROW 144                       // bytes per K/V smem row (72 bf16)
#define ABUF  (64 * AKROW)              // bytes per buffer per matrix
#define ATTN_SMEM (6 * ABUF)            // 3 buffers x (K + V)

__global__ void __launch_bounds__(256) attn_kernel()
{
    extern __shared__ char asmem[];
    __nv_bfloat16 (*Ks)[72] = (__nv_bfloat16(*)[72])asmem;
    __nv_bfloat16 (*Vs)[72] = (__nv_bfloat16(*)[72])(asmem + 3 * ABUF);

    const int tid  = threadIdx.x;
    const int lane = tid & 31;
    const int wq   = tid >> 5;
    const int g    = lane >> 2;
    const int tg   = lane & 3;
    const int qb   = blockIdx.x;
    const int bh   = blockIdx.y;
    const int t0   = qb * 128;
    const int w    = t0 >> 9;
    const int rstart = (w > 0) ? 0 : ((512 - (t0 & 511)) >> 6);

    uint32_t vsb   = (uint32_t)__cvta_generic_to_shared(&Vs[0][0]);
    uint32_t vAddr = vsb + (uint32_t)(((lane >> 3) & 1) * 8 + (lane & 7)) * AKROW
                         + (uint32_t)(lane >> 4) * 16;

    unsigned qf[4][4];
    {
        const __nv_bfloat16* qb0 = g_q + ((size_t)bh * SEQ + t0 + wq * 16) * DH;
        #pragma unroll
        for (int kc = 0; kc < 4; kc++) {
            qf[kc][0] = *(const unsigned*)&qb0[(size_t)g * DH + kc * 16 + 2 * tg];
            qf[kc][1] = *(const unsigned*)&qb0[(size_t)(g + 8) * DH + kc * 16 + 2 * tg];
            qf[kc][2] = *(const unsigned*)&qb0[(size_t)g * DH + kc * 16 + 2 * tg + 8];
            qf[kc][3] = *(const unsigned*)&qb0[(size_t)(g + 8) * DH + kc * 16 + 2 * tg + 8];
        }
    }

    float o[8][4];
    #pragma unroll
    for (int i = 0; i < 8; i++)
        #pragma unroll
        for (int j = 0; j < 4; j++) o[i][j] = 0.0f;
    float d0 = 0.0f, d1 = 0.0f;

    const __nv_bfloat16* kbase = g_k + (size_t)bh * SEQ * DH;
    const __nv_bfloat16* vbase = g_v + (size_t)bh * SEQ * DH;

    auto stage = [&](int buf, int r) {
        int kg0 = t0 - 512 + 64 * r;
        #pragma unroll
        for (int i = 0; i < 2; i++) {
            int idx = i * 256 + tid;
            int kk = idx >> 3, d8 = (idx & 7) * 8;
            cp16(&Ks[buf * 64 + kk][d8], kbase + (size_t)(kg0 + kk) * DH + d8);
            cp16(&Vs[buf * 64 + kk][d8], vbase + (size_t)(kg0 + kk) * DH + d8);
        }
        cp_commit();
    };

    stage(0, rstart);
    if (rstart + 1 <= 9) stage(1, rstart + 1);

    const int q0r = wq * 16 + g;

    for (int r = rstart; r <= 9; r++) {
        int i  = r - rstart;
        int bi = i % 3;
        if (r < 9) { cp_wait<1>(); } else { cp_wait<0>(); }
        __syncthreads();
        if (r + 2 <= 9) stage((i + 2) % 3, r + 2);

        float s[8][4];
        #pragma unroll
        for (int ii = 0; ii < 8; ii++)
            #pragma unroll
            for (int j = 0; j < 4; j++) s[ii][j] = 0.0f;

        #pragma unroll
        for (int kc = 0; kc < 4; kc++) {
            #pragma unroll
            for (int nf = 0; nf < 8; nf++) {
                unsigned b[2];
                const __nv_bfloat16* kr = &Ks[bi * 64 + nf * 8 + g][kc * 16 + 2 * tg];
                b[0] = *(const unsigned*)kr;
                b[1] = *(const unsigned*)(kr + 8);
                mma_bf16(s[nf], qf[kc], b);
            }
        }

        float p[8][4];
        #pragma unroll
        for (int nf = 0; nf < 8; nf++) {
            int j0  = nf * 8 + 2 * tg;
            int jr0 = 64 * r - 512 + j0;
            int jr1 = jr0 + 1;
            bool ok0 = (jr0 <= q0r)     && (jr0 >= q0r - 512);
            bool ok1 = (jr1 <= q0r)     && (jr1 >= q0r - 512);
            bool ok2 = (jr0 <= q0r + 8) && (jr0 >= q0r - 504);
            bool ok3 = (jr1 <= q0r + 8) && (jr1 >= q0r - 504);
            p[nf][0] = ok0 ? ex2f(s[nf][0]) : 0.0f;
            p[nf][1] = ok1 ? ex2f(s[nf][1]) : 0.0f;
            p[nf][2] = ok2 ? ex2f(s[nf][2]) : 0.0f;
            p[nf][3] = ok3 ? ex2f(s[nf][3]) : 0.0f;
            d0 += p[nf][0] + p[nf][1];
            d1 += p[nf][2] + p[nf][3];
        }

        uint32_t vbufAddr = vAddr + (uint32_t)bi * ABUF;
        #pragma unroll
        for (int kc = 0; kc < 4; kc++) {
            unsigned a[4];
            a[0] = packbf2(p[2 * kc][0],     p[2 * kc][1]);
            a[1] = packbf2(p[2 * kc][2],     p[2 * kc][3]);
            a[2] = packbf2(p[2 * kc + 1][0], p[2 * kc + 1][1]);
            a[3] = packbf2(p[2 * kc + 1][2], p[2 * kc + 1][3]);
            #pragma unroll
            for (int nfp = 0; nfp < 4; nfp++) {
                unsigned bv[4];
                ldsm_x4_t(bv, vbufAddr + (uint32_t)kc * (16 * AKROW) + (uint32_t)nfp * 32);
                mma_bf16(o[2 * nfp],     a, &bv[0]);
                mma_bf16(o[2 * nfp + 1], a, &bv[2]);
            }
        }
    }

    d0 += __shfl_xor_sync(0xffffffffu, d0, 1);
    d0 += __shfl_xor_sync(0xffffffffu, d0, 2);
    d1 += __shfl_xor_sync(0xffffffffu, d1, 1);
    d1 += __shfl_xor_sync(0xffffffffu, d1, 2);
    float i0 = 1.0f / d0, i1 = 1.0f / d1;

    int b = bh >> 3, h = bh & 7;
    int row0 = t0 + wq * 16 + g;
    __nv_bfloat16* ob = g_o + (size_t)b * SEQ * DMODEL + h * DH;
    #pragma unroll
    for (int nf = 0; nf < 8; nf++) {
        int col = nf * 8 + 2 * tg;
        __nv_bfloat162 lo, hi;
        lo.x = __float2bfloat16(o[nf][0] * i0);
        lo.y = __float2bfloat16(o[nf][1] * i0);
        hi.x = __float2bfloat16(o[nf][2] * i1);
        hi.y = __float2bfloat16(o[nf][3] * i1);
        *(__nv_bfloat162*)&ob[(size_t)row0 * DMODEL + col]       = lo;
        *(__nv_bfloat162*)&ob[(size_t)(row0 + 8) * DMODEL + col] = hi;
    }
}

// ---------------- launch ----------------
extern "C" void kernel_launch(void* const* d_in, const int* in_sizes, int n_in,
                              void* d_out, int out_size)
{
    const float* x     = (const float*)d_in[0];
    const float* ln1g  = (const float*)d_in[1];
    const float* ln1b  = (const float*)d_in[2];
    const float* Wqkv  = (const float*)d_in[3];
    const float* qsc   = (const float*)d_in[4];
    const float* ksc   = (const float*)d_in[5];
    const float* Wout  = (const float*)d_in[6];
    const float* ln2g  = (const float*)d_in[7];
    const float* ln2b  = (const float*)d_in[8];
    const float* W1    = (const float*)d_in[9];
    const float* b1    = (const float*)d_in[10];
    const float* W2    = (const float*)d_in[11];
    const float* b2    = (const float*)d_in[12];
    float* out = (float*)d_out;

    __nv_bfloat16 *ph, *po, *pg, *pWqkvT, *pWoutT, *pW1iT, *pW2T;
    float *px1, *pb1i;
    cudaGetSymbolAddress((void**)&ph,     g_h);
    cudaGetSymbolAddress((void**)&po,     g_o);
    cudaGetSymbolAddress((void**)&px1,    g_x1);
    cudaGetSymbolAddress((void**)&pg,     g_gate);
    cudaGetSymbolAddress((void**)&pWqkvT, g_WqkvT);
    cudaGetSymbolAddress((void**)&pWoutT, g_WoutT);
    cudaGetSymbolAddress((void**)&pW1iT,  g_W1iT);
    cudaGetSymbolAddress((void**)&pW2T,   g_W2T);
    cudaGetSymbolAddress((void**)&pb1i,   g_b1i);

    cudaFuncSetAttribute(gemm_bf16<0>, cudaFuncAttributeMaxDynamicSharedMemorySize, GEMM_SMEM);
    cudaFuncSetAttribute(gemm_bf16<1>, cudaFuncAttributeMaxDynamicSharedMemorySize, GEMM_SMEM);
    cudaFuncSetAttribute(gemm_bf16<2>, cudaFuncAttributeMaxDynamicSharedMemorySize, GEMM_SMEM);
    cudaFuncSetAttribute(gemm_bf16<3>, cudaFuncAttributeMaxDynamicSharedMemorySize, GEMM_SMEM);
    cudaFuncSetAttribute(gemm_bf16<5>, cudaFuncAttributeMaxDynamicSharedMemorySize, GEMM_SMEM);
    cudaFuncSetAttribute(attn_kernel,  cudaFuncAttributeMaxDynamicSharedMemorySize, ATTN_SMEM);

    // 0) weight prep + rotary table
    {
        dim3 blk(32, 8);
        transpose_bf16_k<false><<<dim3(QKVN / 32, DMODEL / 32), blk>>>(
            Wqkv, pWqkvT, DMODEL, QKVN, DMODEL);
        transpose_bf16_k<false><<<dim3(DMODEL / 32, DMODEL / 32), blk>>>(
            Wout, pWoutT, DMODEL, DMODEL, DMODEL);
        transpose_bf16_k<true><<<dim3(HID2P / 32, DMODEL / 32), blk>>>(
            W1, pW1iT, DMODEL, HID2, DMODEL);
        transpose_bf16_k<false><<<dim3(DMODEL / 32, KFF2 / 32), blk>>>(
            W2, pW2T, HID, DMODEL, KFF2);
        b1i_kernel<<<(HID2P + 255) / 256, 256>>>(b1);
        rot_table_kernel<<<(32 * SEQ) / 256, 256>>>();
    }

    // 1) LN1 -> h (bf16)
    ln_kernel<<<BNROWS, 256>>>(x, ln1g, ln1b, ph);
    // 2) QKV GEMM + fused split/l2norm/rotary (table) -> g_q, g_k, g_v
    gemm_bf16<5><<<dim3(QKVN / 128, BNROWS / 128), 256, GEMM_SMEM>>>(
        ph, pWqkvT, qsc, ksc, nullptr, DMODEL, DMODEL, DMODEL, 0);
    // 3) local attention -> o (bf16)
    attn_kernel<<<dim3(SEQ / 128, BHEADS), 256, ATTN_SMEM>>>();
    // 4) out projection + residual -> x1 (fp32)
    gemm_bf16<1><<<dim3(DMODEL / 128, BNROWS / 128), 256, GEMM_SMEM>>>(
        po, pWoutT, nullptr, x, px1, DMODEL, DMODEL, DMODEL, DMODEL);
    // 5) LN2 -> h (bf16)
    ln_kernel<<<BNROWS, 256>>>(px1, ln2g, ln2b, ph);
    // 6) FF1 + fused geglu -> gate (bf16, bounced stores)
    gemm_bf16<2><<<dim3(HID2P / 128, BNROWS / 128), 256, GEMM_SMEM>>>(
        ph, pW1iT, pb1i, nullptr, (float*)pg, DMODEL, DMODEL, DMODEL, KFF2);
    // 7) FF2 + b2 + residual -> out
    gemm_bf16<3><<<dim3(DMODEL / 128, BNROWS / 128), 256, GEMM_SMEM>>>(
        pg, pW2T, b2, px1, out, KFF2, KFF2, KFF2, DMODEL);
}

// round 14
// speedup vs baseline: 1.0910x; 1.0463x over previous
#include <cuda_runtime.h>
#include <cuda_bf16.h>
#include <math.h>
#include <stdint.h>

// ---------------- problem constants ----------------
#define BATCH   2
#define SEQ     8192
#define DMODEL  512
#define NH      8
#define DH      64
#define BHEADS  16
#define BNROWS  16384
#define QKVN    1536
#define HID     1365
#define HID2    2730
#define HID2P   2816
#define KFF2    1408
#define WSIZE   512

// ---------------- scratch buffers ----------------
__device__ __nv_bfloat16 g_h   [(size_t)BNROWS * DMODEL];
__device__ __nv_bfloat16 g_q   [(size_t)BHEADS * SEQ * DH];   // pre-scaled by 8*log2e
__device__ __nv_bfloat16 g_k   [(size_t)BHEADS * SEQ * DH];
__device__ __nv_bfloat16 g_v   [(size_t)BHEADS * SEQ * DH];
__device__ __nv_bfloat16 g_o   [(size_t)BNROWS * DMODEL];
__device__ float         g_x1  [(size_t)BNROWS * DMODEL];
__device__ __nv_bfloat16 g_gate[(size_t)BNROWS * KFF2];
__device__ __nv_bfloat16 g_WqkvT[(size_t)QKVN * DMODEL];
__device__ __nv_bfloat16 g_WoutT[(size_t)DMODEL * DMODEL];
__device__ __nv_bfloat16 g_W1iT [(size_t)HID2P * DMODEL];
__device__ __nv_bfloat16 g_W2T  [(size_t)DMODEL * KFF2];
__device__ float         g_b1i  [HID2P];
__device__ float4        g_rot  [(size_t)32 * SEQ];   // [d][n]: cos, sin, QSC*xs, 1/xs

// ---------------- helpers ----------------
__device__ __forceinline__ float ex2f(float x) {
    float y;
    asm("ex2.approx.f32 %0, %1;" : "=f"(y) : "f"(x));
    return y;
}
__device__ __forceinline__ void mma_bf16(float c[4], const unsigned a[4], const unsigned b[2]) {
    asm volatile(
        "mma.sync.aligned.m16n8k16.row.col.f32.bf16.bf16.f32 "
        "{%0,%1,%2,%3}, {%4,%5,%6,%7}, {%8,%9}, {%0,%1,%2,%3};"
        : "+f"(c[0]), "+f"(c[1]), "+f"(c[2]), "+f"(c[3])
        : "r"(a[0]), "r"(a[1]), "r"(a[2]), "r"(a[3]), "r"(b[0]), "r"(b[1]));
}
__device__ __forceinline__ void ldsm_x4(unsigned r[4], uint32_t addr) {
    asm volatile("ldmatrix.sync.aligned.m8n8.x4.shared.b16 {%0,%1,%2,%3}, [%4];"
                 : "=r"(r[0]), "=r"(r[1]), "=r"(r[2]), "=r"(r[3]) : "r"(addr));
}
__device__ __forceinline__ void ldsm_x4_t(unsigned r[4], uint32_t addr) {
    asm volatile("ldmatrix.sync.aligned.m8n8.x4.trans.shared.b16 {%0,%1,%2,%3}, [%4];"
                 : "=r"(r[0]), "=r"(r[1]), "=r"(r[2]), "=r"(r[3]) : "r"(addr));
}
__device__ __forceinline__ unsigned packbf2(float lo, float hi) {
    unsigned d;
    asm("cvt.rn.bf16x2.f32 %0, %1, %2;" : "=r"(d) : "f"(hi), "f"(lo));
    return d;
}
__device__ __forceinline__ void cp16(const void* s, const void* g) {
    unsigned sa = (unsigned)__cvta_generic_to_shared(s);
    asm volatile("cp.async.cg.shared.global [%0], [%1], 16;" :: "r"(sa), "l"(g));
}
__device__ __forceinline__ void cp_commit() { asm volatile("cp.async.commit_group;"); }
template<int NN> __device__ __forceinline__ void cp_wait() {
    asm volatile("cp.async.wait_group %0;" :: "n"(NN));
}

// ---------------- unified prep kernel (all weight transposes + b1i + rot table) ----
struct PrepArgs {
    const float *Wqkv, *Wout, *W1, *W2, *b1;
};

__device__ void transpose_body(const float* __restrict__ src, __nv_bfloat16* __restrict__ dst,
                               int Ksrc, int Nsrc, int Kpad, bool remap, int bx, int by)
{
    __shared__ float t[32][33];
    int n0 = bx * 32, k0 = by * 32;
    int x = threadIdx.x, y = threadIdx.y;
    #pragma unroll
    for (int i = 0; i < 32; i += 8) {
        int k = k0 + y + i, j = n0 + x;
        int c = remap ? ((j >> 1) + (j & 1) * HID) : j;
        int nlim = remap ? HID2 : Nsrc;
        t[y + i][x] = (k < Ksrc && j < nlim) ? src[(size_t)k * Nsrc + c] : 0.0f;
    }
    __syncthreads();
    #pragma unroll
    for (int i = 0; i < 32; i += 8) {
        int n = n0 + y + i, k = k0 + x;
        dst[(size_t)n * Kpad + k] = __float2bfloat16(t[x][y + i]);
    }
}

// grid: 768 + 256 + 1408 + 704 + 11 + 1024 = 4171 blocks of (32,8)
#define PREP_BLOCKS 4171
__global__ void prep_all(PrepArgs pa)
{
    int blk = blockIdx.x;
    if (blk < 768)  { transpose_body(pa.Wqkv, g_WqkvT, DMODEL, QKVN,  DMODEL, false, blk % 48, blk / 48); return; }
    blk -= 768;
    if (blk < 256)  { transpose_body(pa.Wout, g_WoutT, DMODEL, DMODEL, DMODEL, false, blk % 16, blk / 16); return; }
    blk -= 256;
    if (blk < 1408) { transpose_body(pa.W1,   g_W1iT,  DMODEL, HID2,  DMODEL, true,  blk % 88, blk / 88); return; }
    blk -= 1408;
    if (blk < 704)  { transpose_body(pa.W2,   g_W2T,   HID,    DMODEL, KFF2,  false, blk % 16, blk / 16); return; }
    blk -= 704;
    int tid = threadIdx.y * 32 + threadIdx.x;
    if (blk < 11) {
        int j = blk * 256 + tid;
        if (j < HID2P) g_b1i[j] = (j < HID2) ? pa.b1[(j >> 1) + (j & 1) * HID] : 0.0f;
        return;
    }
    blk -= 11;
    {   // rotary table [d][n]
        int idx = blk * 256 + tid;
        int d = idx >> 13;
        int n = idx & (SEQ - 1);
        float invf = exp2f((float)d * (-13.287712379549449f / 32.0f));
        float fr = (float)n * invf;
        float cs = cosf(fr), sn = sinf(fr);
        float sv = (2.0f * (float)d + 0.4f * 64.0f) / (1.4f * 64.0f);
        float pw = ((float)n - (float)(SEQ / 2)) / (float)(WSIZE / 2);
        float xs = exp2f(pw * log2f(sv));
        g_rot[idx] = make_float4(cs, sn, 11.541560327111708f * xs, 1.0f / xs);
    }
}

// ---------------- LayerNorm (emits bf16) ----------------
__global__ void ln_kernel(const float* __restrict__ x,
                          const float* __restrict__ gamma,
                          const float* __restrict__ beta,
                          __nv_bfloat16* __restrict__ out)
{
    int row = blockIdx.x;
    int tid = threadIdx.x;
    const float* xr = x + (size_t)row * DMODEL;
    float v0 = xr[tid];
    float v1 = xr[tid + 256];
    float s  = v0 + v1;
    float ss = v0 * v0 + v1 * v1;

    __shared__ float shs[8], shss[8];
    #pragma unroll
    for (int o = 16; o > 0; o >>= 1) {
        s  += __shfl_down_sync(0xffffffffu, s,  o);
        ss += __shfl_down_sync(0xffffffffu, ss, o);
    }
    if ((tid & 31) == 0) { shs[tid >> 5] = s; shss[tid >> 5] = ss; }
    __syncthreads();
    if (tid < 8) {
        s = shs[tid]; ss = shss[tid];
        #pragma unroll
        for (int o = 4; o > 0; o >>= 1) {
            s  += __shfl_down_sync(0xffu, s,  o);
            ss += __shfl_down_sync(0xffu, ss, o);
        }
        if (tid == 0) { shs[0] = s; shss[0] = ss; }
    }
    __syncthreads();
    float mean = shs[0]  * (1.0f / DMODEL);
    float var  = shss[0] * (1.0f / DMODEL) - mean * mean;
    float inv  = rsqrtf(var + 1e-5f);
    __nv_bfloat16* outr = out + (size_t)row * DMODEL;
    outr[tid]       = __float2bfloat16((v0 - mean) * inv * gamma[tid]       + beta[tid]);
    outr[tid + 256] = __float2bfloat16((v1 - mean) * inv * gamma[tid + 256] + beta[tid + 256]);
}

// ---------------- bf16 mma GEMM, 128x128 tile, 4-stage, ldmatrix fragments ----------------
// MODE: 0 f32 out; 1 +res; 2 +bias geglu->bf16 half-width (smem-bounced);
//       3 +bias+res; 5 fused qkv split + l2norm + rotary via table (smem-bounced)
#define GROWB 80                   // bytes per smem row (40 bf16)
#define GSTGB (128 * GROWB)        // bytes per stage (A or B)
#define GEMM_SMEM (8 * GSTGB)      // 4 stages x (A + B)

template<int MODE>
__global__ void __launch_bounds__(256, 2)
gemm_bf16(const __nv_bfloat16* __restrict__ A, const __nv_bfloat16* __restrict__ BT,
          const float* __restrict__ bias, const float* __restrict__ res,
          float* __restrict__ C, int K, int lda, int ldb, int ldc)
{
    extern __shared__ __nv_bfloat16 smem[];
    __nv_bfloat16 (*As)[40] = (__nv_bfloat16(*)[40])smem;
    __nv_bfloat16 (*Bs)[40] = (__nv_bfloat16(*)[40])(smem + 4 * 128 * 40);

    int tid  = threadIdx.x;
    int lane = tid & 31;
    int wid  = tid >> 5;
    int g  = lane >> 2;
    int tg = lane & 3;
    int wm = (wid & 1) * 64;
    int wn = (wid >> 1) * 32;
    int m0 = blockIdx.y * 128, n0 = blockIdx.x * 128;

    uint32_t smb   = (uint32_t)__cvta_generic_to_shared(smem);
    uint32_t aAddr = smb + (uint32_t)(wm + ((lane >> 3) & 1) * 8 + (lane & 7)) * GROWB
                         + (uint32_t)(lane >> 4) * 16;
    uint32_t bAddr = smb + 4 * GSTGB
                         + (uint32_t)(wn + ((lane >> 4) & 1) * 8 + (lane & 7)) * GROWB
                         + (uint32_t)((lane >> 3) & 1) * 16;

    float c[4][4][4];
    #pragma unroll
    for (int i = 0; i < 4; i++)
        #pragma unroll
        for (int j = 0; j < 4; j++)
            #pragma unroll
            for (int l = 0; l < 4; l++) c[i][j][l] = 0.0f;

    int T = K >> 5;

    auto stage = [&](int st, int k0) {
        #pragma unroll
        for (int i = 0; i < 2; i++) {
            int idx = i * 256 + tid;
            int row = idx >> 2, c8 = (idx & 3) * 8;
            cp16(&As[st * 128 + row][c8], A + (size_t)(m0 + row) * lda + k0 + c8);
            cp16(&Bs[st * 128 + row][c8], BT + (size_t)(n0 + row) * ldb + k0 + c8);
        }
        cp_commit();
    };

    stage(0, 0);
    if (T > 1) stage(1, 32);
    if (T > 2) stage(2, 64);

    for (int kt = 0; kt < T; kt++) {
        if (kt + 2 < T)      { cp_wait<2>(); }
        else if (kt + 1 < T) { cp_wait<1>(); }
        else                 { cp_wait<0>(); }
        __syncthreads();
        if (kt + 3 < T) stage((kt + 3) & 3, (kt + 3) * 32);

        uint32_t stOff = (uint32_t)(kt & 3) * GSTGB;
        #pragma unroll
        for (int ks = 0; ks < 2; ks++) {
            uint32_t kb = ks * 32;
            unsigned a[4][4], bq[2][4];
            #pragma unroll
            for (int mf = 0; mf < 4; mf++)
                ldsm_x4(a[mf], aAddr + stOff + mf * (16 * GROWB) + kb);
            #pragma unroll
            for (int nfp = 0; nfp < 2; nfp++)
                ldsm_x4(bq[nfp], bAddr + stOff + nfp * (16 * GROWB) + kb);
            #pragma unroll
            for (int mf = 0; mf < 4; mf++)
                #pragma unroll
                for (int nf = 0; nf < 4; nf++)
                    mma_bf16(c[mf][nf], a[mf], &bq[nf >> 1][(nf & 1) * 2]);
        }
    }

    if (MODE == 2 || MODE == 5) {
        __syncthreads();   // all warps done reading stage smem
        if (MODE == 2) {
            __nv_bfloat16* Cb = (__nv_bfloat16*)C;
            __nv_bfloat16 (*sm2)[72] = (__nv_bfloat16(*)[72])smem;
            #pragma unroll
            for (int mf = 0; mf < 4; mf++) {
                #pragma unroll
                for (int nf = 0; nf < 4; nf++) {
                    int lc = wn / 2 + nf * 4 + tg;
                    #pragma unroll
                    for (int half = 0; half < 2; half++) {
                        int lr = wm + mf * 16 + g + half * 8;
                        int col = n0 + wn + nf * 8 + 2 * tg;
                        float xa = c[mf][nf][half * 2]     + bias[col];
                        float yg = c[mf][nf][half * 2 + 1] + bias[col + 1];
                        float ge = 0.5f * yg * (1.0f + erff(yg * 0.70710678118654752f));
                        sm2[lr][lc] = __float2bfloat16(xa * ge);
                    }
                }
            }
            __syncthreads();
            #pragma unroll
            for (int it = 0; it < 4; it++) {
                int idx = it * 256 + tid;
                int lr = idx >> 3, ch = idx & 7;
                *(float4*)&Cb[(size_t)(m0 + lr) * ldc + (n0 >> 1) + ch * 8] =
                    *(const float4*)&sm2[lr][ch * 8];
            }
        } else {
            // MODE 5: fused qkv split + l2norm + scale + rotary (table-driven)
            __nv_bfloat16 (*sm4)[136] = (__nv_bfloat16(*)[136])smem;
            #pragma unroll
            for (int mf = 0; mf < 4; mf++) {
                #pragma unroll
                for (int nf = 0; nf < 4; nf++) {
                    int lc = wn + nf * 8 + 2 * tg;
                    #pragma unroll
                    for (int half = 0; half < 2; half++) {
                        int lr = wm + mf * 16 + g + half * 8;
                        __nv_bfloat162 o2;
                        o2.x = __float2bfloat16(c[mf][nf][half * 2]);
                        o2.y = __float2bfloat16(c[mf][nf][half * 2 + 1]);
                        *(__nv_bfloat162*)&sm4[lr][lc] = o2;
                    }
                }
            }
            __syncthreads();

            int lr  = tid >> 1;
            int hh  = tid & 1;
            int row = m0 + lr;
            int b   = row >> 13;             // / SEQ
            int n   = row & (SEQ - 1);
            int sect = n0 >> 9;              // 0=q, 1=k, 2=v
            int h    = ((n0 & 511) >> 6) + hh;
            size_t obase = ((size_t)(b * NH + h) * SEQ + n) * DH;
            const __nv_bfloat16* src = &sm4[lr][hh * 64];

            if (sect == 2) {
                __nv_bfloat16* dst = g_v + obase;
                #pragma unroll
                for (int i = 0; i < 8; i++)
                    *(float4*)&dst[i * 8] = *(const float4*)&src[i * 8];
            } else {
                float sumsq = 0.0f;
                #pragma unroll
                for (int i = 0; i < 8; i++) {
                    uint4 v4 = *(const uint4*)&src[i * 8];
                    #pragma unroll
                    for (int j = 0; j < 4; j++) {
                        unsigned u = (&v4.x)[j];
                        __nv_bfloat162 t2 = *(__nv_bfloat162*)&u;
                        float lo = __bfloat162float(t2.x);
                        float hi = __bfloat162float(t2.y);
                        sumsq = fmaf(lo, lo, sumsq);
                        sumsq = fmaf(hi, hi, sumsq);
                    }
                }
                float inv = 1.0f / fmaxf(sqrtf(sumsq), 1e-12f);
                const float* scale = (sect == 0) ? bias : res;
                __nv_bfloat16* dst = ((sect == 0) ? g_q : g_k) + obase;

                #pragma unroll
                for (int i = 0; i < 4; i++) {
                    unsigned lo4[4], hi4[4];
                    #pragma unroll
                    for (int j = 0; j < 4; j++) {
                        int d0 = 8 * i + 2 * j;
                        __nv_bfloat162 ta = *(const __nv_bfloat162*)&src[d0];
                        __nv_bfloat162 tb = *(const __nv_bfloat162*)&src[d0 + 32];
                        float4 r0 = g_rot[(size_t)d0 * SEQ + n];
                        float4 r1 = g_rot[(size_t)(d0 + 1) * SEQ + n];
                        float va0 = __bfloat162float(ta.x) * inv * scale[d0];
                        float va1 = __bfloat162float(ta.y) * inv * scale[d0 + 1];
                        float vb0 = __bfloat162float(tb.x) * inv * scale[d0 + 32];
                        float vb1 = __bfloat162float(tb.y) * inv * scale[d0 + 33];
                        float m0v = (sect == 0) ? r0.z : r0.w;
                        float m1v = (sect == 0) ? r1.z : r1.w;
                        float o00 = (va0 * r0.x - vb0 * r0.y) * m0v;
                        float o01 = (va1 * r1.x - vb1 * r1.y) * m1v;
                        float o10 = (vb0 * r0.x + va0 * r0.y) * m0v;
                        float o11 = (vb1 * r1.x + va1 * r1.y) * m1v;
                        lo4[j] = packbf2(o00, o01);
                        hi4[j] = packbf2(o10, o11);
                    }
                    *(uint4*)&dst[8 * i]      = make_uint4(lo4[0], lo4[1], lo4[2], lo4[3]);
                    *(uint4*)&dst[32 + 8 * i] = make_uint4(hi4[0], hi4[1], hi4[2], hi4[3]);
                }
            }
        }
        return;
    }

    #pragma unroll
    for (int mf = 0; mf < 4; mf++) {
        int r0 = m0 + wm + mf * 16 + g;
        #pragma unroll
        for (int nf = 0; nf < 4; nf++) {
            int col = n0 + wn + nf * 8 + 2 * tg;
            #pragma unroll
            for (int half = 0; half < 2; half++) {
                int r = r0 + half * 8;
                float cx = c[mf][nf][half * 2];
                float cy = c[mf][nf][half * 2 + 1];
                if (MODE == 0) {
                    *(float2*)&C[(size_t)r * ldc + col] = make_float2(cx, cy);
                } else if (MODE == 1) {
                    float2 rr = *(const float2*)&res[(size_t)r * ldc + col];
                    *(float2*)&C[(size_t)r * ldc + col] =
                        make_float2(cx + rr.x, cy + rr.y);
                } else {
                    float2 rr = *(const float2*)&res[(size_t)r * ldc + col];
                    *(float2*)&C[(size_t)r * ldc + col] =
                        make_float2(cx + bias[col] + rr.x,
                                    cy + bias[col + 1] + rr.y);
                }
            }
        }
    }
}

// ---------------- local windowed attention: all-ldmatrix fragments, mask elision ----
#define AKROW 144                       // bytes per K/V smem row (72 bf16)
#define ABUF  (64 * AKROW)              // bytes per buffer per matrix
#define ATTN_SMEM (6 * ABUF)            // 3 buffers x (K + V)

__global__ void __launch_bounds__(256) attn_kernel()
{
    extern __shared__ char asmem[];
    __nv_bfloat16 (*Ks)[72] = (__nv_bfloat16(*)[72])asmem;
    __nv_bfloat16 (*Vs)[72] = (__nv_bfloat16(*)[72])(asmem + 3 * ABUF);

    const int tid  = threadIdx.x;
    const int lane = tid & 31;
    const int wq   = tid >> 5;
    const int g    = lane >> 2;
    const int tg   = lane & 3;
    const int qb   = blockIdx.x;
    const int bh   = blockIdx.y;
    const int t0   = qb * 128;
    const int w    = t0 >> 9;
    const int rstart = (w > 0) ? 0 : ((512 - (t0 & 511)) >> 6);

    uint32_t ksb   = (uint32_t)__cvta_generic_to_shared(&Ks[0][0]);
    uint32_t kAddr = ksb + (uint32_t)(((lane >> 4) & 1) * 8 + (lane & 7)) * AKROW
                         + (uint32_t)((lane >> 3) & 1) * 16;
    uint32_t vsb   = (uint32_t)__cvta_generic_to_shared(&Vs[0][0]);
    uint32_t vAddr = vsb + (uint32_t)(((lane >> 3) & 1) * 8 + (lane & 7)) * AKROW
                         + (uint32_t)(lane >> 4) * 16;

    unsigned qf[4][4];
    {
        const __nv_bfloat16* qb0 = g_q + ((size_t)bh * SEQ + t0 + wq * 16) * DH;
        #pragma unroll
        for (int kc = 0; kc < 4; kc++) {
            qf[kc][0] = *(const unsigned*)&qb0[(size_t)g * DH + kc * 16 + 2 * tg];
            qf[kc][1] = *(const unsigned*)&qb0[(size_t)(g + 8) * DH + kc * 16 + 2 * tg];
            qf[kc][2] = *(const unsigned*)&qb0[(size_t)g * DH + kc * 16 + 2 * tg + 8];
            qf[kc][3] = *(const unsigned*)&qb0[(size_t)(g + 8) * DH + kc * 16 + 2 * tg + 8];
        }
    }

    float o[8][4];
    #pragma unroll
    for (int i = 0; i < 8; i++)
        #pragma unroll
        for (int j = 0; j < 4; j++) o[i][j] = 0.0f;
    float d0 = 0.0f, d1 = 0.0f;

    const __nv_bfloat16* kbase = g_k + (size_t)bh * SEQ * DH;
    const __nv_bfloat16* vbase = g_v + (size_t)bh * SEQ * DH;

    auto stage = [&](int buf, int r) {
        int kg0 = t0 - 512 + 64 * r;
        #pragma unroll
        for (int i = 0; i < 2; i++) {
            int idx = i * 256 + tid;
            int kk = idx >> 3, d8 = (idx & 7) * 8;
            cp16(&Ks[buf * 64 + kk][d8], kbase + (size_t)(kg0 + kk) * DH + d8);
            cp16(&Vs[buf * 64 + kk][d8], vbase + (size_t)(kg0 + kk) * DH + d8);
        }
        cp_commit();
    };

    stage(0, rstart);
    if (rstart + 1 <= 9) stage(1, rstart + 1);

    const int q0r = wq * 16 + g;

    for (int r = rstart; r <= 9; r++) {
        int i  = r - rstart;
        int bi = i % 3;
        if (r < 9) { cp_wait<1>(); } else { cp_wait<0>(); }
        __syncthreads();
        if (r + 2 <= 9) stage((i + 2) % 3, r + 2);

        // S = Qscaled @ K^T (bf16, K fragments via ldmatrix)
        float s[8][4];
        #pragma unroll
        for (int ii = 0; ii < 8; ii++)
            #pragma unroll
            for (int j = 0; j < 4; j++) s[ii][j] = 0.0f;

        uint32_t kbufAddr = kAddr + (uint32_t)bi * ABUF;
        #pragma unroll
        for (int kc = 0; kc < 4; kc++) {
            #pragma unroll
            for (int nfp = 0; nfp < 4; nfp++) {
                unsigned kq[4];
                ldsm_x4(kq, kbufAddr + (uint32_t)nfp * (16 * AKROW) + (uint32_t)kc * 32);
                mma_bf16(s[2 * nfp],     qf[kc], &kq[0]);
                mma_bf16(s[2 * nfp + 1], qf[kc], &kq[2]);
            }
        }

        // exp2 (+ mask only on boundary tiles r<=1 or r>=8)
        float p[8][4];
        if (r >= 2 && r <= 7) {
            #pragma unroll
            for (int nf = 0; nf < 8; nf++) {
                p[nf][0] = ex2f(s[nf][0]);
                p[nf][1] = ex2f(s[nf][1]);
                p[nf][2] = ex2f(s[nf][2]);
                p[nf][3] = ex2f(s[nf][3]);
                d0 += p[nf][0] + p[nf][1];
                d1 += p[nf][2] + p[nf][3];
            }
        } else {
            #pragma unroll
            for (int nf = 0; nf < 8; nf++) {
                int j0  = nf * 8 + 2 * tg;
                int jr0 = 64 * r - 512 + j0;
                int jr1 = jr0 + 1;
                bool ok0 = (jr0 <= q0r)     && (jr0 >= q0r - 512);
                bool ok1 = (jr1 <= q0r)     && (jr1 >= q0r - 512);
                bool ok2 = (jr0 <= q0r + 8) && (jr0 >= q0r - 504);
                bool ok3 = (jr1 <= q0r + 8) && (jr1 >= q0r - 504);
                p[nf][0] = ok0 ? ex2f(s[nf][0]) : 0.0f;
                p[nf][1] = ok1 ? ex2f(s[nf][1]) : 0.0f;
                p[nf][2] = ok2 ? ex2f(s[nf][2]) : 0.0f;
                p[nf][3] = ok3 ? ex2f(s[nf][3]) : 0.0f;
                d0 += p[nf][0] + p[nf][1];
                d1 += p[nf][2] + p[nf][3];
            }
        }

        // O += P @ V (bf16; V fragments via ldmatrix.trans)
        uint32_t vbufAddr = vAddr + (uint32_t)bi * ABUF;
        #pragma unroll
        for (int kc = 0; kc < 4; kc++) {
            unsigned a[4];
            a[0] = packbf2(p[2 * kc][0],     p[2 * kc][1]);
            a[1] = packbf2(p[2 * kc][2],     p[2 * kc][3]);
            a[2] = packbf2(p[2 * kc + 1][0], p[2 * kc + 1][1]);
            a[3] = packbf2(p[2 * kc + 1][2], p[2 * kc + 1][3]);
            #pragma unroll
            for (int nfp = 0; nfp < 4; nfp++) {
                unsigned bv[4];
                ldsm_x4_t(bv, vbufAddr + (uint32_t)kc * (16 * AKROW) + (uint32_t)nfp * 32);
                mma_bf16(o[2 * nfp],     a, &bv[0]);
                mma_bf16(o[2 * nfp + 1], a, &bv[2]);
            }
        }
    }

    d0 += __shfl_xor_sync(0xffffffffu, d0, 1);
    d0 += __shfl_xor_sync(0xffffffffu, d0, 2);
    d1 += __shfl_xor_sync(0xffffffffu, d1, 1);
    d1 += __shfl_xor_sync(0xffffffffu, d1, 2);
    float i0 = 1.0f / d0, i1 = 1.0f / d1;

    int b = bh >> 3, h = bh & 7;
    int row0 = t0 + wq * 16 + g;
    __nv_bfloat16* ob = g_o + (size_t)b * SEQ * DMODEL + h * DH;
    #pragma unroll
    for (int nf = 0; nf < 8; nf++) {
        int col = nf * 8 + 2 * tg;
        __nv_bfloat162 lo, hi;
        lo.x = __float2bfloat16(o[nf][0] * i0);
        lo.y = __float2bfloat16(o[nf][1] * i0);
        hi.x = __float2bfloat16(o[nf][2] * i1);
        hi.y = __float2bfloat16(o[nf][3] * i1);
        *(__nv_bfloat162*)&ob[(size_t)row0 * DMODEL + col]       = lo;
        *(__nv_bfloat162*)&ob[(size_t)(row0 + 8) * DMODEL + col] = hi;
    }
}

// ---------------- launch ----------------
extern "C" void kernel_launch(void* const* d_in, const int* in_sizes, int n_in,
                              void* d_out, int out_size)
{
    const float* x     = (const float*)d_in[0];
    const float* ln1g  = (const float*)d_in[1];
    const float* ln1b  = (const float*)d_in[2];
    const float* Wqkv  = (const float*)d_in[3];
    const float* qsc   = (const float*)d_in[4];
    const float* ksc   = (const float*)d_in[5];
    const float* Wout  = (const float*)d_in[6];
    const float* ln2g  = (const float*)d_in[7];
    const float* ln2b  = (const float*)d_in[8];
    const float* W1    = (const float*)d_in[9];
    const float* b1    = (const float*)d_in[10];
    const float* W2    = (const float*)d_in[11];
    const float* b2    = (const float*)d_in[12];
    float* out = (float*)d_out;

    __nv_bfloat16 *ph, *po, *pg, *pWqkvT, *pWoutT, *pW1iT, *pW2T;
    float *px1, *pb1i;
    cudaGetSymbolAddress((void**)&ph,     g_h);
    cudaGetSymbolAddress((void**)&po,     g_o);
    cudaGetSymbolAddress((void**)&px1,    g_x1);
    cudaGetSymbolAddress((void**)&pg,     g_gate);
    cudaGetSymbolAddress((void**)&pWqkvT, g_WqkvT);
    cudaGetSymbolAddress((void**)&pWoutT, g_WoutT);
    cudaGetSymbolAddress((void**)&pW1iT,  g_W1iT);
    cudaGetSymbolAddress((void**)&pW2T,   g_W2T);
    cudaGetSymbolAddress((void**)&pb1i,   g_b1i);

    cudaFuncSetAttribute(gemm_bf16<0>, cudaFuncAttributeMaxDynamicSharedMemorySize, GEMM_SMEM);
    cudaFuncSetAttribute(gemm_bf16<1>, cudaFuncAttributeMaxDynamicSharedMemorySize, GEMM_SMEM);
    cudaFuncSetAttribute(gemm_bf16<2>, cudaFuncAttributeMaxDynamicSharedMemorySize, GEMM_SMEM);
    cudaFuncSetAttribute(gemm_bf16<3>, cudaFuncAttributeMaxDynamicSharedMemorySize, GEMM_SMEM);
    cudaFuncSetAttribute(gemm_bf16<5>, cudaFuncAttributeMaxDynamicSharedMemorySize, GEMM_SMEM);
    cudaFuncSetAttribute(attn_kernel,  cudaFuncAttributeMaxDynamicSharedMemorySize, ATTN_SMEM);

    // 0) unified prep (weight transposes + b1 interleave + rotary table)
    {
        PrepArgs pa;
        pa.Wqkv = Wqkv; pa.Wout = Wout; pa.W1 = W1; pa.W2 = W2; pa.b1 = b1;
        prep_all<<<PREP_BLOCKS, dim3(32, 8)>>>(pa);
    }

    // 1) LN1 -> h (bf16)
    ln_kernel<<<BNROWS, 256>>>(x, ln1g, ln1b, ph);
    // 2) QKV GEMM + fused split/l2norm/rotary (table) -> g_q, g_k, g_v
    gemm_bf16<5><<<dim3(QKVN / 128, BNROWS / 128), 256, GEMM_SMEM>>>(
        ph, pWqkvT, qsc, ksc, nullptr, DMODEL, DMODEL, DMODEL, 0);
    // 3) local attention -> o (bf16)
    attn_kernel<<<dim3(SEQ / 128, BHEADS), 256, ATTN_SMEM>>>();
    // 4) out projection + residual -> x1 (fp32)
    gemm_bf16<1><<<dim3(DMODEL / 128, BNROWS / 128), 256, GEMM_SMEM>>>(
        po, pWoutT, nullptr, x, px1, DMODEL, DMODEL, DMODEL, DMODEL);
    // 5) LN2 -> h (bf16)
    ln_kernel<<<BNROWS, 256>>>(px1, ln2g, ln2b, ph);
    // 6) FF1 + fused geglu -> gate (bf16, bounced stores)
    gemm_bf16<2><<<dim3(HID2P / 128, BNROWS / 128), 256, GEMM_SMEM>>>(
        ph, pW1iT, pb1i, nullptr, (float*)pg, DMODEL, DMODEL, DMODEL, KFF2);
    // 7) FF2 + b2 + residual -> out
    gemm_bf16<3><<<dim3(DMODEL / 128, BNROWS / 128), 256, GEMM_SMEM>>>(
        pg, pW2T, b2, px1, out, KFF2, KFF2, KFF2, DMODEL);
}

// round 15
// speedup vs baseline: 1.1802x; 1.0818x over previous
#include <cuda_runtime.h>
#include <cuda_bf16.h>
#include <math.h>
#include <stdint.h>

// ---------------- problem constants ----------------
#define BATCH   2
#define SEQ     8192
#define DMODEL  512
#define NH      8
#define DH      64
#define BHEADS  16
#define BNROWS  16384
#define QKVN    1536
#define HID     1365
#define HID2    2730
#define HID2P   2816
#define KFF2    1408
#define WSIZE   512

// ---------------- scratch buffers ----------------
__device__ __nv_bfloat16 g_h   [(size_t)BNROWS * DMODEL];
__device__ __nv_bfloat16 g_q   [(size_t)BHEADS * SEQ * DH];   // pre-scaled by 8*log2e
__device__ __nv_bfloat16 g_k   [(size_t)BHEADS * SEQ * DH];
__device__ __nv_bfloat16 g_v   [(size_t)BHEADS * SEQ * DH];
__device__ __nv_bfloat16 g_o   [(size_t)BNROWS * DMODEL];
__device__ float         g_x1  [(size_t)BNROWS * DMODEL];
__device__ __nv_bfloat16 g_gate[(size_t)BNROWS * KFF2];
__device__ __nv_bfloat16 g_WqkvT[(size_t)QKVN * DMODEL];
__device__ __nv_bfloat16 g_WoutT[(size_t)DMODEL * DMODEL];
__device__ __nv_bfloat16 g_W1iT [(size_t)HID2P * DMODEL];
__device__ __nv_bfloat16 g_W2T  [(size_t)DMODEL * KFF2];
__device__ float         g_b1i  [HID2P];
__device__ float4        g_rot  [(size_t)32 * SEQ];   // [d][n]: cos, sin, QSC*xs, 1/xs

// ---------------- helpers ----------------
__device__ __forceinline__ float ex2f(float x) {
    float y;
    asm("ex2.approx.f32 %0, %1;" : "=f"(y) : "f"(x));
    return y;
}
__device__ __forceinline__ void mma_bf16(float c[4], const unsigned a[4], const unsigned b[2]) {
    asm volatile(
        "mma.sync.aligned.m16n8k16.row.col.f32.bf16.bf16.f32 "
        "{%0,%1,%2,%3}, {%4,%5,%6,%7}, {%8,%9}, {%0,%1,%2,%3};"
        : "+f"(c[0]), "+f"(c[1]), "+f"(c[2]), "+f"(c[3])
        : "r"(a[0]), "r"(a[1]), "r"(a[2]), "r"(a[3]), "r"(b[0]), "r"(b[1]));
}
__device__ __forceinline__ void ldsm_x4(unsigned r[4], uint32_t addr) {
    asm volatile("ldmatrix.sync.aligned.m8n8.x4.shared.b16 {%0,%1,%2,%3}, [%4];"
                 : "=r"(r[0]), "=r"(r[1]), "=r"(r[2]), "=r"(r[3]) : "r"(addr));
}
__device__ __forceinline__ void ldsm_x4_t(unsigned r[4], uint32_t addr) {
    asm volatile("ldmatrix.sync.aligned.m8n8.x4.trans.shared.b16 {%0,%1,%2,%3}, [%4];"
                 : "=r"(r[0]), "=r"(r[1]), "=r"(r[2]), "=r"(r[3]) : "r"(addr));
}
__device__ __forceinline__ unsigned packbf2(float lo, float hi) {
    unsigned d;
    asm("cvt.rn.bf16x2.f32 %0, %1, %2;" : "=r"(d) : "f"(hi), "f"(lo));
    return d;
}
__device__ __forceinline__ void cp16(const void* s, const void* g) {
    unsigned sa = (unsigned)__cvta_generic_to_shared(s);
    asm volatile("cp.async.cg.shared.global [%0], [%1], 16;" :: "r"(sa), "l"(g));
}
__device__ __forceinline__ void cp_commit() { asm volatile("cp.async.commit_group;"); }
template<int NN> __device__ __forceinline__ void cp_wait() {
    asm volatile("cp.async.wait_group %0;" :: "n"(NN));
}

// ---------------- unified prep kernel ----------------
struct PrepArgs {
    const float *Wqkv, *Wout, *W1, *W2, *b1;
};

__device__ void transpose_body(const float* __restrict__ src, __nv_bfloat16* __restrict__ dst,
                               int Ksrc, int Nsrc, int Kpad, bool remap, int bx, int by)
{
    __shared__ float t[32][33];
    int n0 = bx * 32, k0 = by * 32;
    int x = threadIdx.x, y = threadIdx.y;
    #pragma unroll
    for (int i = 0; i < 32; i += 8) {
        int k = k0 + y + i, j = n0 + x;
        int c = remap ? ((j >> 1) + (j & 1) * HID) : j;
        int nlim = remap ? HID2 : Nsrc;
        t[y + i][x] = (k < Ksrc && j < nlim) ? src[(size_t)k * Nsrc + c] : 0.0f;
    }
    __syncthreads();
    #pragma unroll
    for (int i = 0; i < 32; i += 8) {
        int n = n0 + y + i, k = k0 + x;
        dst[(size_t)n * Kpad + k] = __float2bfloat16(t[x][y + i]);
    }
}

#define PREP_BLOCKS 4171
__global__ void prep_all(PrepArgs pa)
{
    int blk = blockIdx.x;
    if (blk < 768)  { transpose_body(pa.Wqkv, g_WqkvT, DMODEL, QKVN,  DMODEL, false, blk % 48, blk / 48); return; }
    blk -= 768;
    if (blk < 256)  { transpose_body(pa.Wout, g_WoutT, DMODEL, DMODEL, DMODEL, false, blk % 16, blk / 16); return; }
    blk -= 256;
    if (blk < 1408) { transpose_body(pa.W1,   g_W1iT,  DMODEL, HID2,  DMODEL, true,  blk % 88, blk / 88); return; }
    blk -= 1408;
    if (blk < 704)  { transpose_body(pa.W2,   g_W2T,   HID,    DMODEL, KFF2,  false, blk % 16, blk / 16); return; }
    blk -= 704;
    int tid = threadIdx.y * 32 + threadIdx.x;
    if (blk < 11) {
        int j = blk * 256 + tid;
        if (j < HID2P) g_b1i[j] = (j < HID2) ? pa.b1[(j >> 1) + (j & 1) * HID] : 0.0f;
        return;
    }
    blk -= 11;
    {
        int idx = blk * 256 + tid;
        int d = idx >> 13;
        int n = idx & (SEQ - 1);
        float invf = exp2f((float)d * (-13.287712379549449f / 32.0f));
        float fr = (float)n * invf;
        float cs = cosf(fr), sn = sinf(fr);
        float sv = (2.0f * (float)d + 0.4f * 64.0f) / (1.4f * 64.0f);
        float pw = ((float)n - (float)(SEQ / 2)) / (float)(WSIZE / 2);
        float xs = exp2f(pw * log2f(sv));
        g_rot[idx] = make_float4(cs, sn, 11.541560327111708f * xs, 1.0f / xs);
    }
}

// ---------------- LayerNorm: warp-per-row, 8 rows/block ----------------
__global__ void ln_kernel(const float* __restrict__ x,
                          const float* __restrict__ gamma,
                          const float* __restrict__ beta,
                          __nv_bfloat16* __restrict__ out)
{
    int warp = threadIdx.x >> 5;
    int lane = threadIdx.x & 31;
    int row  = blockIdx.x * 8 + warp;
    const float4* xr = (const float4*)(x + (size_t)row * DMODEL);

    float4 v[4];
    float s = 0.0f, ss = 0.0f;
    #pragma unroll
    for (int i = 0; i < 4; i++) {
        v[i] = xr[lane + 32 * i];
        s  += v[i].x + v[i].y + v[i].z + v[i].w;
        ss += v[i].x * v[i].x + v[i].y * v[i].y + v[i].z * v[i].z + v[i].w * v[i].w;
    }
    #pragma unroll
    for (int o = 16; o > 0; o >>= 1) {
        s  += __shfl_xor_sync(0xffffffffu, s,  o);
        ss += __shfl_xor_sync(0xffffffffu, ss, o);
    }
    float mean = s * (1.0f / DMODEL);
    float var  = ss * (1.0f / DMODEL) - mean * mean;
    float inv  = rsqrtf(var + 1e-5f);

    const float4* g4 = (const float4*)gamma;
    const float4* b4 = (const float4*)beta;
    __nv_bfloat16* outr = out + (size_t)row * DMODEL;
    #pragma unroll
    for (int i = 0; i < 4; i++) {
        float4 gg = g4[lane + 32 * i];
        float4 bb = b4[lane + 32 * i];
        unsigned p0 = packbf2((v[i].x - mean) * inv * gg.x + bb.x,
                              (v[i].y - mean) * inv * gg.y + bb.y);
        unsigned p1 = packbf2((v[i].z - mean) * inv * gg.z + bb.z,
                              (v[i].w - mean) * inv * gg.w + bb.w);
        *(uint2*)&outr[(lane + 32 * i) * 4] = make_uint2(p0, p1);
    }
}

// ---------------- bf16 mma GEMM, 128x128 tile, BK=64, 3-stage ----------------
// MODE: 0 f32 out; 1 +res; 2 +bias geglu->bf16 half-width (smem-bounced);
//       3 +bias+res; 5 fused qkv split + l2norm + rotary via table (smem-bounced)
#define AROWB 144                       // bytes per smem row (72 bf16, 64 data + pad)
#define GSTGB (128 * AROWB)             // 18432 B per stage (A or B)
#define GEMM_SMEM (6 * GSTGB)           // 3 stages x (A + B) = 110592 B

template<int MODE>
__global__ void __launch_bounds__(256, 2)
gemm_bf16(const __nv_bfloat16* __restrict__ A, const __nv_bfloat16* __restrict__ BT,
          const float* __restrict__ bias, const float* __restrict__ res,
          float* __restrict__ C, int K, int lda, int ldb, int ldc)
{
    extern __shared__ __nv_bfloat16 smem[];
    __nv_bfloat16 (*As)[72] = (__nv_bfloat16(*)[72])smem;
    __nv_bfloat16 (*Bs)[72] = (__nv_bfloat16(*)[72])(smem + 3 * 128 * 72);

    int tid  = threadIdx.x;
    int lane = tid & 31;
    int wid  = tid >> 5;
    int g  = lane >> 2;
    int tg = lane & 3;
    int wm = (wid & 1) * 64;
    int wn = (wid >> 1) * 32;
    int m0 = blockIdx.y * 128, n0 = blockIdx.x * 128;

    uint32_t smb   = (uint32_t)__cvta_generic_to_shared(smem);
    uint32_t aAddr = smb + (uint32_t)(wm + ((lane >> 3) & 1) * 8 + (lane & 7)) * AROWB
                         + (uint32_t)(lane >> 4) * 16;
    uint32_t bAddr = smb + 3 * GSTGB
                         + (uint32_t)(wn + ((lane >> 4) & 1) * 8 + (lane & 7)) * AROWB
                         + (uint32_t)((lane >> 3) & 1) * 16;

    float c[4][4][4];
    #pragma unroll
    for (int i = 0; i < 4; i++)
        #pragma unroll
        for (int j = 0; j < 4; j++)
            #pragma unroll
            for (int l = 0; l < 4; l++) c[i][j][l] = 0.0f;

    int T = K >> 6;

    auto stage = [&](int st, int k0) {
        #pragma unroll
        for (int i = 0; i < 4; i++) {
            int idx = i * 256 + tid;
            int row = idx >> 3, ch = (idx & 7) * 8;
            cp16(&As[st * 128 + row][ch], A + (size_t)(m0 + row) * lda + k0 + ch);
        }
        #pragma unroll
        for (int i = 0; i < 4; i++) {
            int idx = i * 256 + tid;
            int row = idx >> 3, ch = (idx & 7) * 8;
            cp16(&Bs[st * 128 + row][ch], BT + (size_t)(n0 + row) * ldb + k0 + ch);
        }
        cp_commit();
    };

    stage(0, 0);
    if (T > 1) stage(1, 64);

    for (int kt = 0; kt < T; kt++) {
        if (kt + 1 < T) { cp_wait<1>(); } else { cp_wait<0>(); }
        __syncthreads();
        if (kt + 2 < T) stage((kt + 2) % 3, (kt + 2) * 64);

        uint32_t stOff = (uint32_t)(kt % 3) * GSTGB;
        #pragma unroll
        for (int ks = 0; ks < 4; ks++) {
            uint32_t kb = ks * 32;
            unsigned a[4][4], bq[2][4];
            #pragma unroll
            for (int mf = 0; mf < 4; mf++)
                ldsm_x4(a[mf], aAddr + stOff + mf * (16 * AROWB) + kb);
            #pragma unroll
            for (int nfp = 0; nfp < 2; nfp++)
                ldsm_x4(bq[nfp], bAddr + stOff + nfp * (16 * AROWB) + kb);
            #pragma unroll
            for (int mf = 0; mf < 4; mf++)
                #pragma unroll
                for (int nf = 0; nf < 4; nf++)
                    mma_bf16(c[mf][nf], a[mf], &bq[nf >> 1][(nf & 1) * 2]);
        }
    }

    if (MODE == 2 || MODE == 5) {
        __syncthreads();   // all warps done reading stage smem
        if (MODE == 2) {
            __nv_bfloat16* Cb = (__nv_bfloat16*)C;
            __nv_bfloat16 (*sm2)[72] = (__nv_bfloat16(*)[72])smem;
            #pragma unroll
            for (int mf = 0; mf < 4; mf++) {
                #pragma unroll
                for (int nf = 0; nf < 4; nf++) {
                    int lc = wn / 2 + nf * 4 + tg;
                    #pragma unroll
                    for (int half = 0; half < 2; half++) {
                        int lr = wm + mf * 16 + g + half * 8;
                        int col = n0 + wn + nf * 8 + 2 * tg;
                        float xa = c[mf][nf][half * 2]     + bias[col];
                        float yg = c[mf][nf][half * 2 + 1] + bias[col + 1];
                        float ge = 0.5f * yg * (1.0f + erff(yg * 0.70710678118654752f));
                        sm2[lr][lc] = __float2bfloat16(xa * ge);
                    }
                }
            }
            __syncthreads();
            #pragma unroll
            for (int it = 0; it < 4; it++) {
                int idx = it * 256 + tid;
                int lr = idx >> 3, ch = idx & 7;
                *(float4*)&Cb[(size_t)(m0 + lr) * ldc + (n0 >> 1) + ch * 8] =
                    *(const float4*)&sm2[lr][ch * 8];
            }
        } else {
            // MODE 5: fused qkv split + l2norm + scale + rotary (table-driven)
            __nv_bfloat16 (*sm4)[136] = (__nv_bfloat16(*)[136])smem;
            #pragma unroll
            for (int mf = 0; mf < 4; mf++) {
                #pragma unroll
                for (int nf = 0; nf < 4; nf++) {
                    int lc = wn + nf * 8 + 2 * tg;
                    #pragma unroll
                    for (int half = 0; half < 2; half++) {
                        int lr = wm + mf * 16 + g + half * 8;
                        __nv_bfloat162 o2;
                        o2.x = __float2bfloat16(c[mf][nf][half * 2]);
                        o2.y = __float2bfloat16(c[mf][nf][half * 2 + 1]);
                        *(__nv_bfloat162*)&sm4[lr][lc] = o2;
                    }
                }
            }
            __syncthreads();

            int lr  = tid >> 1;
            int hh  = tid & 1;
            int row = m0 + lr;
            int b   = row >> 13;
            int n   = row & (SEQ - 1);
            int sect = n0 >> 9;              // 0=q, 1=k, 2=v
            int h    = ((n0 & 511) >> 6) + hh;
            size_t obase = ((size_t)(b * NH + h) * SEQ + n) * DH;
            const __nv_bfloat16* src = &sm4[lr][hh * 64];

            if (sect == 2) {
                __nv_bfloat16* dst = g_v + obase;
                #pragma unroll
                for (int i = 0; i < 8; i++)
                    *(float4*)&dst[i * 8] = *(const float4*)&src[i * 8];
            } else {
                float sumsq = 0.0f;
                #pragma unroll
                for (int i = 0; i < 8; i++) {
                    uint4 v4 = *(const uint4*)&src[i * 8];
                    #pragma unroll
                    for (int j = 0; j < 4; j++) {
                        unsigned u = (&v4.x)[j];
                        __nv_bfloat162 t2 = *(__nv_bfloat162*)&u;
                        float lo = __bfloat162float(t2.x);
                        float hi = __bfloat162float(t2.y);
                        sumsq = fmaf(lo, lo, sumsq);
                        sumsq = fmaf(hi, hi, sumsq);
                    }
                }
                float inv = 1.0f / fmaxf(sqrtf(sumsq), 1e-12f);
                const float* scale = (sect == 0) ? bias : res;
                __nv_bfloat16* dst = ((sect == 0) ? g_q : g_k) + obase;

                #pragma unroll
                for (int i = 0; i < 4; i++) {
                    unsigned lo4[4], hi4[4];
                    #pragma unroll
                    for (int j = 0; j < 4; j++) {
                        int d0 = 8 * i + 2 * j;
                        __nv_bfloat162 ta = *(const __nv_bfloat162*)&src[d0];
                        __nv_bfloat162 tb = *(const __nv_bfloat162*)&src[d0 + 32];
                        float4 r0 = g_rot[(size_t)d0 * SEQ + n];
                        float4 r1 = g_rot[(size_t)(d0 + 1) * SEQ + n];
                        float va0 = __bfloat162float(ta.x) * inv * scale[d0];
                        float va1 = __bfloat162float(ta.y) * inv * scale[d0 + 1];
                        float vb0 = __bfloat162float(tb.x) * inv * scale[d0 + 32];
                        float vb1 = __bfloat162float(tb.y) * inv * scale[d0 + 33];
                        float m0v = (sect == 0) ? r0.z : r0.w;
                        float m1v = (sect == 0) ? r1.z : r1.w;
                        float o00 = (va0 * r0.x - vb0 * r0.y) * m0v;
                        float o01 = (va1 * r1.x - vb1 * r1.y) * m1v;
                        float o10 = (vb0 * r0.x + va0 * r0.y) * m0v;
                        float o11 = (vb1 * r1.x + va1 * r1.y) * m1v;
                        lo4[j] = packbf2(o00, o01);
                        hi4[j] = packbf2(o10, o11);
                    }
                    *(uint4*)&dst[8 * i]      = make_uint4(lo4[0], lo4[1], lo4[2], lo4[3]);
                    *(uint4*)&dst[32 + 8 * i] = make_uint4(hi4[0], hi4[1], hi4[2], hi4[3]);
                }
            }
        }
        return;
    }

    #pragma unroll
    for (int mf = 0; mf < 4; mf++) {
        int r0 = m0 + wm + mf * 16 + g;
        #pragma unroll
        for (int nf = 0; nf < 4; nf++) {
            int col = n0 + wn + nf * 8 + 2 * tg;
            #pragma unroll
            for (int half = 0; half < 2; half++) {
                int r = r0 + half * 8;
                float cx = c[mf][nf][half * 2];
                float cy = c[mf][nf][half * 2 + 1];
                if (MODE == 0) {
                    *(float2*)&C[(size_t)r * ldc + col] = make_float2(cx, cy);
                } else if (MODE == 1) {
                    float2 rr = *(const float2*)&res[(size_t)r * ldc + col];
                    *(float2*)&C[(size_t)r * ldc + col] =
                        make_float2(cx + rr.x, cy + rr.y);
                } else {
                    float2 rr = *(const float2*)&res[(size_t)r * ldc + col];
                    *(float2*)&C[(size_t)r * ldc + col] =
                        make_float2(cx + bias[col] + rr.x,
                                    cy + bias[col + 1] + rr.y);
                }
            }
        }
    }
}

// ---------------- local windowed attention: all-ldmatrix fragments, mask elision ----
#define AKROW 144
#define ABUF  (64 * AKROW)
#define ATTN_SMEM (6 * ABUF)

__global__ void __launch_bounds__(256) attn_kernel()
{
    extern __shared__ char asmem[];
    __nv_bfloat16 (*Ks)[72] = (__nv_bfloat16(*)[72])asmem;
    __nv_bfloat16 (*Vs)[72] = (__nv_bfloat16(*)[72])(asmem + 3 * ABUF);

    const int tid  = threadIdx.x;
    const int lane = tid & 31;
    const int wq   = tid >> 5;
    const int g    = lane >> 2;
    const int tg   = lane & 3;
    const int qb   = blockIdx.x;
    const int bh   = blockIdx.y;
    const int t0   = qb * 128;
    const int w    = t0 >> 9;
    const int rstart = (w > 0) ? 0 : ((512 - (t0 & 511)) >> 6);

    uint32_t ksb   = (uint32_t)__cvta_generic_to_shared(&Ks[0][0]);
    uint32_t kAddr = ksb + (uint32_t)(((lane >> 4) & 1) * 8 + (lane & 7)) * AKROW
                         + (uint32_t)((lane >> 3) & 1) * 16;
    uint32_t vsb   = (uint32_t)__cvta_generic_to_shared(&Vs[0][0]);
    uint32_t vAddr = vsb + (uint32_t)(((lane >> 3) & 1) * 8 + (lane & 7)) * AKROW
                         + (uint32_t)(lane >> 4) * 16;

    unsigned qf[4][4];
    {
        const __nv_bfloat16* qb0 = g_q + ((size_t)bh * SEQ + t0 + wq * 16) * DH;
        #pragma unroll
        for (int kc = 0; kc < 4; kc++) {
            qf[kc][0] = *(const unsigned*)&qb0[(size_t)g * DH + kc * 16 + 2 * tg];
            qf[kc][1] = *(const unsigned*)&qb0[(size_t)(g + 8) * DH + kc * 16 + 2 * tg];
            qf[kc][2] = *(const unsigned*)&qb0[(size_t)g * DH + kc * 16 + 2 * tg + 8];
            qf[kc][3] = *(const unsigned*)&qb0[(size_t)(g + 8) * DH + kc * 16 + 2 * tg + 8];
        }
    }

    float o[8][4];
    #pragma unroll
    for (int i = 0; i < 8; i++)
        #pragma unroll
        for (int j = 0; j < 4; j++) o[i][j] = 0.0f;
    float d0 = 0.0f, d1 = 0.0f;

    const __nv_bfloat16* kbase = g_k + (size_t)bh * SEQ * DH;
    const __nv_bfloat16* vbase = g_v + (size_t)bh * SEQ * DH;

    auto stage = [&](int buf, int r) {
        int kg0 = t0 - 512 + 64 * r;
        #pragma unroll
        for (int i = 0; i < 2; i++) {
            int idx = i * 256 + tid;
            int kk = idx >> 3, d8 = (idx & 7) * 8;
            cp16(&Ks[buf * 64 + kk][d8], kbase + (size_t)(kg0 + kk) * DH + d8);
            cp16(&Vs[buf * 64 + kk][d8], vbase + (size_t)(kg0 + kk) * DH + d8);
        }
        cp_commit();
    };

    stage(0, rstart);
    if (rstart + 1 <= 9) stage(1, rstart + 1);

    const int q0r = wq * 16 + g;

    for (int r = rstart; r <= 9; r++) {
        int i  = r - rstart;
        int bi = i % 3;
        if (r < 9) { cp_wait<1>(); } else { cp_wait<0>(); }
        __syncthreads();
        if (r + 2 <= 9) stage((i + 2) % 3, r + 2);

        float s[8][4];
        #pragma unroll
        for (int ii = 0; ii < 8; ii++)
            #pragma unroll
            for (int j = 0; j < 4; j++) s[ii][j] = 0.0f;

        uint32_t kbufAddr = kAddr + (uint32_t)bi * ABUF;
        #pragma unroll
        for (int kc = 0; kc < 4; kc++) {
            #pragma unroll
            for (int nfp = 0; nfp < 4; nfp++) {
                unsigned kq[4];
                ldsm_x4(kq, kbufAddr + (uint32_t)nfp * (16 * AKROW) + (uint32_t)kc * 32);
                mma_bf16(s[2 * nfp],     qf[kc], &kq[0]);
                mma_bf16(s[2 * nfp + 1], qf[kc], &kq[2]);
            }
        }

        float p[8][4];
        if (r >= 2 && r <= 7) {
            #pragma unroll
            for (int nf = 0; nf < 8; nf++) {
                p[nf][0] = ex2f(s[nf][0]);
                p[nf][1] = ex2f(s[nf][1]);
                p[nf][2] = ex2f(s[nf][2]);
                p[nf][3] = ex2f(s[nf][3]);
                d0 += p[nf][0] + p[nf][1];
                d1 += p[nf][2] + p[nf][3];
            }
        } else {
            #pragma unroll
            for (int nf = 0; nf < 8; nf++) {
                int j0  = nf * 8 + 2 * tg;
                int jr0 = 64 * r - 512 + j0;
                int jr1 = jr0 + 1;
                bool ok0 = (jr0 <= q0r)     && (jr0 >= q0r - 512);
                bool ok1 = (jr1 <= q0r)     && (jr1 >= q0r - 512);
                bool ok2 = (jr0 <= q0r + 8) && (jr0 >= q0r - 504);
                bool ok3 = (jr1 <= q0r + 8) && (jr1 >= q0r - 504);
                p[nf][0] = ok0 ? ex2f(s[nf][0]) : 0.0f;
                p[nf][1] = ok1 ? ex2f(s[nf][1]) : 0.0f;
                p[nf][2] = ok2 ? ex2f(s[nf][2]) : 0.0f;
                p[nf][3] = ok3 ? ex2f(s[nf][3]) : 0.0f;
                d0 += p[nf][0] + p[nf][1];
                d1 += p[nf][2] + p[nf][3];
            }
        }

        uint32_t vbufAddr = vAddr + (uint32_t)bi * ABUF;
        #pragma unroll
        for (int kc = 0; kc < 4; kc++) {
            unsigned a[4];
            a[0] = packbf2(p[2 * kc][0],     p[2 * kc][1]);
            a[1] = packbf2(p[2 * kc][2],     p[2 * kc][3]);
            a[2] = packbf2(p[2 * kc + 1][0], p[2 * kc + 1][1]);
            a[3] = packbf2(p[2 * kc + 1][2], p[2 * kc + 1][3]);
            #pragma unroll
            for (int nfp = 0; nfp < 4; nfp++) {
                unsigned bv[4];
                ldsm_x4_t(bv, vbufAddr + (uint32_t)kc * (16 * AKROW) + (uint32_t)nfp * 32);
                mma_bf16(o[2 * nfp],     a, &bv[0]);
                mma_bf16(o[2 * nfp + 1], a, &bv[2]);
            }
        }
    }

    d0 += __shfl_xor_sync(0xffffffffu, d0, 1);
    d0 += __shfl_xor_sync(0xffffffffu, d0, 2);
    d1 += __shfl_xor_sync(0xffffffffu, d1, 1);
    d1 += __shfl_xor_sync(0xffffffffu, d1, 2);
    float i0 = 1.0f / d0, i1 = 1.0f / d1;

    int b = bh >> 3, h = bh & 7;
    int row0 = t0 + wq * 16 + g;
    __nv_bfloat16* ob = g_o + (size_t)b * SEQ * DMODEL + h * DH;
    #pragma unroll
    for (int nf = 0; nf < 8; nf++) {
        int col = nf * 8 + 2 * tg;
        __nv_bfloat162 lo, hi;
        lo.x = __float2bfloat16(o[nf][0] * i0);
        lo.y = __float2bfloat16(o[nf][1] * i0);
        hi.x = __float2bfloat16(o[nf][2] * i1);
        hi.y = __float2bfloat16(o[nf][3] * i1);
        *(__nv_bfloat162*)&ob[(size_t)row0 * DMODEL + col]       = lo;
        *(__nv_bfloat162*)&ob[(size_t)(row0 + 8) * DMODEL + col] = hi;
    }
}

// ---------------- launch ----------------
extern "C" void kernel_launch(void* const* d_in, const int* in_sizes, int n_in,
                              void* d_out, int out_size)
{
    const float* x     = (const float*)d_in[0];
    const float* ln1g  = (const float*)d_in[1];
    const float* ln1b  = (const float*)d_in[2];
    const float* Wqkv  = (const float*)d_in[3];
    const float* qsc   = (const float*)d_in[4];
    const float* ksc   = (const float*)d_in[5];
    const float* Wout  = (const float*)d_in[6];
    const float* ln2g  = (const float*)d_in[7];
    const float* ln2b  = (const float*)d_in[8];
    const float* W1    = (const float*)d_in[9];
    const float* b1    = (const float*)d_in[10];
    const float* W2    = (const float*)d_in[11];
    const float* b2    = (const float*)d_in[12];
    float* out = (float*)d_out;

    __nv_bfloat16 *ph, *po, *pg, *pWqkvT, *pWoutT, *pW1iT, *pW2T;
    float *px1, *pb1i;
    cudaGetSymbolAddress((void**)&ph,     g_h);
    cudaGetSymbolAddress((void**)&po,     g_o);
    cudaGetSymbolAddress((void**)&px1,    g_x1);
    cudaGetSymbolAddress((void**)&pg,     g_gate);
    cudaGetSymbolAddress((void**)&pWqkvT, g_WqkvT);
    cudaGetSymbolAddress((void**)&pWoutT, g_WoutT);
    cudaGetSymbolAddress((void**)&pW1iT,  g_W1iT);
    cudaGetSymbolAddress((void**)&pW2T,   g_W2T);
    cudaGetSymbolAddress((void**)&pb1i,   g_b1i);

    cudaFuncSetAttribute(gemm_bf16<0>, cudaFuncAttributeMaxDynamicSharedMemorySize, GEMM_SMEM);
    cudaFuncSetAttribute(gemm_bf16<1>, cudaFuncAttributeMaxDynamicSharedMemorySize, GEMM_SMEM);
    cudaFuncSetAttribute(gemm_bf16<2>, cudaFuncAttributeMaxDynamicSharedMemorySize, GEMM_SMEM);
    cudaFuncSetAttribute(gemm_bf16<3>, cudaFuncAttributeMaxDynamicSharedMemorySize, GEMM_SMEM);
    cudaFuncSetAttribute(gemm_bf16<5>, cudaFuncAttributeMaxDynamicSharedMemorySize, GEMM_SMEM);
    cudaFuncSetAttribute(attn_kernel,  cudaFuncAttributeMaxDynamicSharedMemorySize, ATTN_SMEM);

    // 0) unified prep
    {
        PrepArgs pa;
        pa.Wqkv = Wqkv; pa.Wout = Wout; pa.W1 = W1; pa.W2 = W2; pa.b1 = b1;
        prep_all<<<PREP_BLOCKS, dim3(32, 8)>>>(pa);
    }

    // 1) LN1 -> h (bf16)
    ln_kernel<<<BNROWS / 8, 256>>>(x, ln1g, ln1b, ph);
    // 2) QKV GEMM + fused split/l2norm/rotary (table) -> g_q, g_k, g_v
    gemm_bf16<5><<<dim3(QKVN / 128, BNROWS / 128), 256, GEMM_SMEM>>>(
        ph, pWqkvT, qsc, ksc, nullptr, DMODEL, DMODEL, DMODEL, 0);
    // 3) local attention -> o (bf16)
    attn_kernel<<<dim3(SEQ / 128, BHEADS), 256, ATTN_SMEM>>>();
    // 4) out projection + residual -> x1 (fp32)
    gemm_bf16<1><<<dim3(DMODEL / 128, BNROWS / 128), 256, GEMM_SMEM>>>(
        po, pWoutT, nullptr, x, px1, DMODEL, DMODEL, DMODEL, DMODEL);
    // 5) LN2 -> h (bf16)
    ln_kernel<<<BNROWS / 8, 256>>>(px1, ln2g, ln2b, ph);
    // 6) FF1 + fused geglu -> gate (bf16, bounced stores)
    gemm_bf16<2><<<dim3(HID2P / 128, BNROWS / 128), 256, GEMM_SMEM>>>(
        ph, pW1iT, pb1i, nullptr, (float*)pg, DMODEL, DMODEL, DMODEL, KFF2);
    // 7) FF2 + b2 + residual -> out
    gemm_bf16<3><<<dim3(DMODEL / 128, BNROWS / 128), 256, GEMM_SMEM>>>(
        pg, pW2T, b2, px1, out, KFF2, KFF2, KFF2, DMODEL);
}

// round 16
// speedup vs baseline: 1.1951x; 1.0127x over previous
#include <cuda_runtime.h>
#include <cuda_bf16.h>
#include <math.h>
#include <stdint.h>

// ---------------- problem constants ----------------
#define BATCH   2
#define SEQ     8192
#define DMODEL  512
#define NH      8
#define DH      64
#define BHEADS  16
#define BNROWS  16384
#define QKVN    1536
#define HID     1365
#define HID2    2730
#define HID2P   2816
#define KFF2    1408
#define WSIZE   512

// ---------------- scratch buffers ----------------
__device__ __nv_bfloat16 g_h   [(size_t)BNROWS * DMODEL];
__device__ __nv_bfloat16 g_q   [(size_t)BHEADS * SEQ * DH];   // pre-scaled by 8*log2e
__device__ __nv_bfloat16 g_k   [(size_t)BHEADS * SEQ * DH];
__device__ __nv_bfloat16 g_v   [(size_t)BHEADS * SEQ * DH];
__device__ __nv_bfloat16 g_o   [(size_t)BNROWS * DMODEL];
__device__ float         g_x1  [(size_t)BNROWS * DMODEL];
__device__ __nv_bfloat16 g_gate[(size_t)BNROWS * KFF2];
__device__ __nv_bfloat16 g_WqkvT[(size_t)QKVN * DMODEL];
__device__ __nv_bfloat16 g_WoutT[(size_t)DMODEL * DMODEL];
__device__ __nv_bfloat16 g_W1iT [(size_t)HID2P * DMODEL];
__device__ __nv_bfloat16 g_W2T  [(size_t)DMODEL * KFF2];
__device__ float         g_b1i  [HID2P];
__device__ float4        g_rot  [(size_t)32 * SEQ];   // [d][n]: cos, sin, QSC*xs, 1/xs

// ---------------- helpers ----------------
__device__ __forceinline__ float ex2f(float x) {
    float y;
    asm("ex2.approx.f32 %0, %1;" : "=f"(y) : "f"(x));
    return y;
}
__device__ __forceinline__ void mma_bf16(float c[4], const unsigned a[4], const unsigned b[2]) {
    asm volatile(
        "mma.sync.aligned.m16n8k16.row.col.f32.bf16.bf16.f32 "
        "{%0,%1,%2,%3}, {%4,%5,%6,%7}, {%8,%9}, {%0,%1,%2,%3};"
        : "+f"(c[0]), "+f"(c[1]), "+f"(c[2]), "+f"(c[3])
        : "r"(a[0]), "r"(a[1]), "r"(a[2]), "r"(a[3]), "r"(b[0]), "r"(b[1]));
}
__device__ __forceinline__ void ldsm_x4(unsigned r[4], uint32_t addr) {
    asm volatile("ldmatrix.sync.aligned.m8n8.x4.shared.b16 {%0,%1,%2,%3}, [%4];"
                 : "=r"(r[0]), "=r"(r[1]), "=r"(r[2]), "=r"(r[3]) : "r"(addr));
}
__device__ __forceinline__ void ldsm_x4_t(unsigned r[4], uint32_t addr) {
    asm volatile("ldmatrix.sync.aligned.m8n8.x4.trans.shared.b16 {%0,%1,%2,%3}, [%4];"
                 : "=r"(r[0]), "=r"(r[1]), "=r"(r[2]), "=r"(r[3]) : "r"(addr));
}
__device__ __forceinline__ unsigned packbf2(float lo, float hi) {
    unsigned d;
    asm("cvt.rn.bf16x2.f32 %0, %1, %2;" : "=r"(d) : "f"(hi), "f"(lo));
    return d;
}
__device__ __forceinline__ void cp16(const void* s, const void* g) {
    unsigned sa = (unsigned)__cvta_generic_to_shared(s);
    asm volatile("cp.async.cg.shared.global [%0], [%1], 16;" :: "r"(sa), "l"(g));
}
__device__ __forceinline__ void cp_commit() { asm volatile("cp.async.commit_group;"); }
template<int NN> __device__ __forceinline__ void cp_wait() {
    asm volatile("cp.async.wait_group %0;" :: "n"(NN));
}

// ---------------- unified prep kernel ----------------
struct PrepArgs {
    const float *Wqkv, *Wout, *W1, *W2, *b1;
};

__device__ void transpose_body(const float* __restrict__ src, __nv_bfloat16* __restrict__ dst,
                               int Ksrc, int Nsrc, int Kpad, bool remap, int bx, int by)
{
    __shared__ float t[32][33];
    int n0 = bx * 32, k0 = by * 32;
    int x = threadIdx.x, y = threadIdx.y;
    #pragma unroll
    for (int i = 0; i < 32; i += 8) {
        int k = k0 + y + i, j = n0 + x;
        int c = remap ? ((j >> 1) + (j & 1) * HID) : j;
        int nlim = remap ? HID2 : Nsrc;
        t[y + i][x] = (k < Ksrc && j < nlim) ? src[(size_t)k * Nsrc + c] : 0.0f;
    }
    __syncthreads();
    #pragma unroll
    for (int i = 0; i < 32; i += 8) {
        int n = n0 + y + i, k = k0 + x;
        dst[(size_t)n * Kpad + k] = __float2bfloat16(t[x][y + i]);
    }
}

#define PREP_BLOCKS 4171
__global__ void prep_all(PrepArgs pa)
{
    int blk = blockIdx.x;
    if (blk < 768)  { transpose_body(pa.Wqkv, g_WqkvT, DMODEL, QKVN,  DMODEL, false, blk % 48, blk / 48); return; }
    blk -= 768;
    if (blk < 256)  { transpose_body(pa.Wout, g_WoutT, DMODEL, DMODEL, DMODEL, false, blk % 16, blk / 16); return; }
    blk -= 256;
    if (blk < 1408) { transpose_body(pa.W1,   g_W1iT,  DMODEL, HID2,  DMODEL, true,  blk % 88, blk / 88); return; }
    blk -= 1408;
    if (blk < 704)  { transpose_body(pa.W2,   g_W2T,   HID,    DMODEL, KFF2,  false, blk % 16, blk / 16); return; }
    blk -= 704;
    int tid = threadIdx.y * 32 + threadIdx.x;
    if (blk < 11) {
        int j = blk * 256 + tid;
        if (j < HID2P) g_b1i[j] = (j < HID2) ? pa.b1[(j >> 1) + (j & 1) * HID] : 0.0f;
        return;
    }
    blk -= 11;
    {
        int idx = blk * 256 + tid;
        int d = idx >> 13;
        int n = idx & (SEQ - 1);
        float invf = exp2f((float)d * (-13.287712379549449f / 32.0f));
        float fr = (float)n * invf;
        float cs = cosf(fr), sn = sinf(fr);
        float sv = (2.0f * (float)d + 0.4f * 64.0f) / (1.4f * 64.0f);
        float pw = ((float)n - (float)(SEQ / 2)) / (float)(WSIZE / 2);
        float xs = exp2f(pw * log2f(sv));
        g_rot[idx] = make_float4(cs, sn, 11.541560327111708f * xs, 1.0f / xs);
    }
}

// ---------------- LayerNorm: warp-per-row, 8 rows/block ----------------
__global__ void ln_kernel(const float* __restrict__ x,
                          const float* __restrict__ gamma,
                          const float* __restrict__ beta,
                          __nv_bfloat16* __restrict__ out)
{
    int warp = threadIdx.x >> 5;
    int lane = threadIdx.x & 31;
    int row  = blockIdx.x * 8 + warp;
    const float4* xr = (const float4*)(x + (size_t)row * DMODEL);

    float4 v[4];
    float s = 0.0f, ss = 0.0f;
    #pragma unroll
    for (int i = 0; i < 4; i++) {
        v[i] = xr[lane + 32 * i];
        s  += v[i].x + v[i].y + v[i].z + v[i].w;
        ss += v[i].x * v[i].x + v[i].y * v[i].y + v[i].z * v[i].z + v[i].w * v[i].w;
    }
    #pragma unroll
    for (int o = 16; o > 0; o >>= 1) {
        s  += __shfl_xor_sync(0xffffffffu, s,  o);
        ss += __shfl_xor_sync(0xffffffffu, ss, o);
    }
    float mean = s * (1.0f / DMODEL);
    float var  = ss * (1.0f / DMODEL) - mean * mean;
    float inv  = rsqrtf(var + 1e-5f);

    const float4* g4 = (const float4*)gamma;
    const float4* b4 = (const float4*)beta;
    __nv_bfloat16* outr = out + (size_t)row * DMODEL;
    #pragma unroll
    for (int i = 0; i < 4; i++) {
        float4 gg = g4[lane + 32 * i];
        float4 bb = b4[lane + 32 * i];
        unsigned p0 = packbf2((v[i].x - mean) * inv * gg.x + bb.x,
                              (v[i].y - mean) * inv * gg.y + bb.y);
        unsigned p1 = packbf2((v[i].z - mean) * inv * gg.z + bb.z,
                              (v[i].w - mean) * inv * gg.w + bb.w);
        *(uint2*)&outr[(lane + 32 * i) * 4] = make_uint2(p0, p1);
    }
}

// ---------------- bf16 mma GEMM, 128x128 tile, BK=64, 3-stage, 4 warps (64x64) ----
// MODE: 0 f32 out; 1 +res; 2 +bias geglu->bf16 half-width (smem-bounced);
//       3 +bias+res; 5 fused qkv split + l2norm + rotary via table (smem-bounced)
#define AROWB 144                       // bytes per smem row (72 bf16, 64 data + pad)
#define GSTGB (128 * AROWB)             // 18432 B per stage (A or B)
#define GEMM_SMEM (6 * GSTGB)           // 3 stages x (A + B) = 110592 B

template<int MODE>
__global__ void __launch_bounds__(128, 2)
gemm_bf16(const __nv_bfloat16* __restrict__ A, const __nv_bfloat16* __restrict__ BT,
          const float* __restrict__ bias, const float* __restrict__ res,
          float* __restrict__ C, int K, int lda, int ldb, int ldc)
{
    extern __shared__ __nv_bfloat16 smem[];
    __nv_bfloat16 (*As)[72] = (__nv_bfloat16(*)[72])smem;
    __nv_bfloat16 (*Bs)[72] = (__nv_bfloat16(*)[72])(smem + 3 * 128 * 72);

    int tid  = threadIdx.x;
    int lane = tid & 31;
    int wid  = tid >> 5;          // 0..3
    int g  = lane >> 2;
    int tg = lane & 3;
    int wm = (wid & 1) * 64;
    int wn = (wid >> 1) * 64;
    int m0 = blockIdx.y * 128, n0 = blockIdx.x * 128;

    uint32_t smb   = (uint32_t)__cvta_generic_to_shared(smem);
    uint32_t aAddr = smb + (uint32_t)(wm + ((lane >> 3) & 1) * 8 + (lane & 7)) * AROWB
                         + (uint32_t)(lane >> 4) * 16;
    uint32_t bAddr = smb + 3 * GSTGB
                         + (uint32_t)(wn + ((lane >> 4) & 1) * 8 + (lane & 7)) * AROWB
                         + (uint32_t)((lane >> 3) & 1) * 16;

    float c[4][8][4];
    #pragma unroll
    for (int i = 0; i < 4; i++)
        #pragma unroll
        for (int j = 0; j < 8; j++)
            #pragma unroll
            for (int l = 0; l < 4; l++) c[i][j][l] = 0.0f;

    int T = K >> 6;

    auto stage = [&](int st, int k0) {
        #pragma unroll
        for (int i = 0; i < 8; i++) {
            int idx = i * 128 + tid;
            int row = idx >> 3, ch = (idx & 7) * 8;
            cp16(&As[st * 128 + row][ch], A + (size_t)(m0 + row) * lda + k0 + ch);
        }
        #pragma unroll
        for (int i = 0; i < 8; i++) {
            int idx = i * 128 + tid;
            int row = idx >> 3, ch = (idx & 7) * 8;
            cp16(&Bs[st * 128 + row][ch], BT + (size_t)(n0 + row) * ldb + k0 + ch);
        }
        cp_commit();
    };

    stage(0, 0);
    if (T > 1) stage(1, 64);

    for (int kt = 0; kt < T; kt++) {
        if (kt + 1 < T) { cp_wait<1>(); } else { cp_wait<0>(); }
        __syncthreads();
        if (kt + 2 < T) stage((kt + 2) % 3, (kt + 2) * 64);

        uint32_t stOff = (uint32_t)(kt % 3) * GSTGB;
        #pragma unroll
        for (int ks = 0; ks < 4; ks++) {
            uint32_t kb = ks * 32;
            unsigned a[4][4], bq[4][4];
            #pragma unroll
            for (int mf = 0; mf < 4; mf++)
                ldsm_x4(a[mf], aAddr + stOff + mf * (16 * AROWB) + kb);
            #pragma unroll
            for (int nfp = 0; nfp < 4; nfp++)
                ldsm_x4(bq[nfp], bAddr + stOff + nfp * (16 * AROWB) + kb);
            #pragma unroll
            for (int mf = 0; mf < 4; mf++)
                #pragma unroll
                for (int nf = 0; nf < 8; nf++)
                    mma_bf16(c[mf][nf], a[mf], &bq[nf >> 1][(nf & 1) * 2]);
        }
    }

    if (MODE == 2 || MODE == 5) {
        __syncthreads();   // all warps done reading stage smem
        if (MODE == 2) {
            __nv_bfloat16* Cb = (__nv_bfloat16*)C;
            __nv_bfloat16 (*sm2)[72] = (__nv_bfloat16(*)[72])smem;
            #pragma unroll
            for (int mf = 0; mf < 4; mf++) {
                #pragma unroll
                for (int nf = 0; nf < 8; nf++) {
                    int lc = wn / 2 + nf * 4 + tg;
                    #pragma unroll
                    for (int half = 0; half < 2; half++) {
                        int lr = wm + mf * 16 + g + half * 8;
                        int col = n0 + wn + nf * 8 + 2 * tg;
                        float xa = c[mf][nf][half * 2]     + bias[col];
                        float yg = c[mf][nf][half * 2 + 1] + bias[col + 1];
                        float ge = 0.5f * yg * (1.0f + erff(yg * 0.70710678118654752f));
                        sm2[lr][lc] = __float2bfloat16(xa * ge);
                    }
                }
            }
            __syncthreads();
            #pragma unroll
            for (int it = 0; it < 8; it++) {
                int idx = it * 128 + tid;
                int lr = idx >> 3, ch = idx & 7;
                *(float4*)&Cb[(size_t)(m0 + lr) * ldc + (n0 >> 1) + ch * 8] =
                    *(const float4*)&sm2[lr][ch * 8];
            }
        } else {
            // MODE 5: fused qkv split + l2norm + scale + rotary (table-driven)
            __nv_bfloat16 (*sm4)[136] = (__nv_bfloat16(*)[136])smem;
            #pragma unroll
            for (int mf = 0; mf < 4; mf++) {
                #pragma unroll
                for (int nf = 0; nf < 8; nf++) {
                    int lc = wn + nf * 8 + 2 * tg;
                    #pragma unroll
                    for (int half = 0; half < 2; half++) {
                        int lr = wm + mf * 16 + g + half * 8;
                        __nv_bfloat162 o2;
                        o2.x = __float2bfloat16(c[mf][nf][half * 2]);
                        o2.y = __float2bfloat16(c[mf][nf][half * 2 + 1]);
                        *(__nv_bfloat162*)&sm4[lr][lc] = o2;
                    }
                }
            }
            __syncthreads();

            int lr  = tid;                   // 0..127
            int row = m0 + lr;
            int b   = row >> 13;
            int n   = row & (SEQ - 1);
            int sect = n0 >> 9;              // 0=q, 1=k, 2=v
            #pragma unroll
            for (int hh = 0; hh < 2; hh++) {
                int h = ((n0 & 511) >> 6) + hh;
                size_t obase = ((size_t)(b * NH + h) * SEQ + n) * DH;
                const __nv_bfloat16* src = &sm4[lr][hh * 64];

                if (sect == 2) {
                    __nv_bfloat16* dst = g_v + obase;
                    #pragma unroll
                    for (int i = 0; i < 8; i++)
                        *(float4*)&dst[i * 8] = *(const float4*)&src[i * 8];
                } else {
                    float sumsq = 0.0f;
                    #pragma unroll
                    for (int i = 0; i < 8; i++) {
                        uint4 v4 = *(const uint4*)&src[i * 8];
                        #pragma unroll
                        for (int j = 0; j < 4; j++) {
                            unsigned u = (&v4.x)[j];
                            __nv_bfloat162 t2 = *(__nv_bfloat162*)&u;
                            float lo = __bfloat162float(t2.x);
                            float hi = __bfloat162float(t2.y);
                            sumsq = fmaf(lo, lo, sumsq);
                            sumsq = fmaf(hi, hi, sumsq);
                        }
                    }
                    float inv = 1.0f / fmaxf(sqrtf(sumsq), 1e-12f);
                    const float* scale = (sect == 0) ? bias : res;
                    __nv_bfloat16* dst = ((sect == 0) ? g_q : g_k) + obase;

                    #pragma unroll
                    for (int i = 0; i < 4; i++) {
                        unsigned lo4[4], hi4[4];
                        #pragma unroll
                        for (int j = 0; j < 4; j++) {
                            int d0 = 8 * i + 2 * j;
                            __nv_bfloat162 ta = *(const __nv_bfloat162*)&src[d0];
                            __nv_bfloat162 tb = *(const __nv_bfloat162*)&src[d0 + 32];
                            float4 r0 = g_rot[(size_t)d0 * SEQ + n];
                            float4 r1 = g_rot[(size_t)(d0 + 1) * SEQ + n];
                            float va0 = __bfloat162float(ta.x) * inv * scale[d0];
                            float va1 = __bfloat162float(ta.y) * inv * scale[d0 + 1];
                            float vb0 = __bfloat162float(tb.x) * inv * scale[d0 + 32];
                            float vb1 = __bfloat162float(tb.y) * inv * scale[d0 + 33];
                            float m0v = (sect == 0) ? r0.z : r0.w;
                            float m1v = (sect == 0) ? r1.z : r1.w;
                            float o00 = (va0 * r0.x - vb0 * r0.y) * m0v;
                            float o01 = (va1 * r1.x - vb1 * r1.y) * m1v;
                            float o10 = (vb0 * r0.x + va0 * r0.y) * m0v;
                            float o11 = (vb1 * r1.x + va1 * r1.y) * m1v;
                            lo4[j] = packbf2(o00, o01);
                            hi4[j] = packbf2(o10, o11);
                        }
                        *(uint4*)&dst[8 * i]      = make_uint4(lo4[0], lo4[1], lo4[2], lo4[3]);
                        *(uint4*)&dst[32 + 8 * i] = make_uint4(hi4[0], hi4[1], hi4[2], hi4[3]);
                    }
                }
            }
        }
        return;
    }

    #pragma unroll
    for (int mf = 0; mf < 4; mf++) {
        int r0 = m0 + wm + mf * 16 + g;
        #pragma unroll
        for (int nf = 0; nf < 8; nf++) {
            int col = n0 + wn + nf * 8 + 2 * tg;
            #pragma unroll
            for (int half = 0; half < 2; half++) {
                int r = r0 + half * 8;
                float cx = c[mf][nf][half * 2];
                float cy = c[mf][nf][half * 2 + 1];
                if (MODE == 0) {
                    *(float2*)&C[(size_t)r * ldc + col] = make_float2(cx, cy);
                } else if (MODE == 1) {
                    float2 rr = *(const float2*)&res[(size_t)r * ldc + col];
                    *(float2*)&C[(size_t)r * ldc + col] =
                        make_float2(cx + rr.x, cy + rr.y);
                } else {
                    float2 rr = *(const float2*)&res[(size_t)r * ldc + col];
                    *(float2*)&C[(size_t)r * ldc + col] =
                        make_float2(cx + bias[col] + rr.x,
                                    cy + bias[col + 1] + rr.y);
                }
            }
        }
    }
}

// ---------------- local windowed attention: all-ldmatrix fragments, mask elision ----
#define AKROW 144
#define ABUF  (64 * AKROW)
#define ATTN_SMEM (6 * ABUF)

__global__ void __launch_bounds__(256) attn_kernel()
{
    extern __shared__ char asmem[];
    __nv_bfloat16 (*Ks)[72] = (__nv_bfloat16(*)[72])asmem;
    __nv_bfloat16 (*Vs)[72] = (__nv_bfloat16(*)[72])(asmem + 3 * ABUF);

    const int tid  = threadIdx.x;
    const int lane = tid & 31;
    const int wq   = tid >> 5;
    const int g    = lane >> 2;
    const int tg   = lane & 3;
    const int qb   = blockIdx.x;
    const int bh   = blockIdx.y;
    const int t0   = qb * 128;
    const int w    = t0 >> 9;
    const int rstart = (w > 0) ? 0 : ((512 - (t0 & 511)) >> 6);

    uint32_t ksb   = (uint32_t)__cvta_generic_to_shared(&Ks[0][0]);
    uint32_t kAddr = ksb + (uint32_t)(((lane >> 4) & 1) * 8 + (lane & 7)) * AKROW
                         + (uint32_t)((lane >> 3) & 1) * 16;
    uint32_t vsb   = (uint32_t)__cvta_generic_to_shared(&Vs[0][0]);
    uint32_t vAddr = vsb + (uint32_t)(((lane >> 3) & 1) * 8 + (lane & 7)) * AKROW
                         + (uint32_t)(lane >> 4) * 16;

    unsigned qf[4][4];
    {
        const __nv_bfloat16* qb0 = g_q + ((size_t)bh * SEQ + t0 + wq * 16) * DH;
        #pragma unroll
        for (int kc = 0; kc < 4; kc++) {
            qf[kc][0] = *(const unsigned*)&qb0[(size_t)g * DH + kc * 16 + 2 * tg];
            qf[kc][1] = *(const unsigned*)&qb0[(size_t)(g + 8) * DH + kc * 16 + 2 * tg];
            qf[kc][2] = *(const unsigned*)&qb0[(size_t)g * DH + kc * 16 + 2 * tg + 8];
            qf[kc][3] = *(const unsigned*)&qb0[(size_t)(g + 8) * DH + kc * 16 + 2 * tg + 8];
        }
    }

    float o[8][4];
    #pragma unroll
    for (int i = 0; i < 8; i++)
        #pragma unroll
        for (int j = 0; j < 4; j++) o[i][j] = 0.0f;
    float d0 = 0.0f, d1 = 0.0f;

    const __nv_bfloat16* kbase = g_k + (size_t)bh * SEQ * DH;
    const __nv_bfloat16* vbase = g_v + (size_t)bh * SEQ * DH;

    auto stage = [&](int buf, int r) {
        int kg0 = t0 - 512 + 64 * r;
        #pragma unroll
        for (int i = 0; i < 2; i++) {
            int idx = i * 256 + tid;
            int kk = idx >> 3, d8 = (idx & 7) * 8;
            cp16(&Ks[buf * 64 + kk][d8], kbase + (size_t)(kg0 + kk) * DH + d8);
            cp16(&Vs[buf * 64 + kk][d8], vbase + (size_t)(kg0 + kk) * DH + d8);
        }
        cp_commit();
    };

    stage(0, rstart);
    if (rstart + 1 <= 9) stage(1, rstart + 1);

    const int q0r = wq * 16 + g;

    for (int r = rstart; r <= 9; r++) {
        int i  = r - rstart;
        int bi = i % 3;
        if (r < 9) { cp_wait<1>(); } else { cp_wait<0>(); }
        __syncthreads();
        if (r + 2 <= 9) stage((i + 2) % 3, r + 2);

        float s[8][4];
        #pragma unroll
        for (int ii = 0; ii < 8; ii++)
            #pragma unroll
            for (int j = 0; j < 4; j++) s[ii][j] = 0.0f;

        uint32_t kbufAddr = kAddr + (uint32_t)bi * ABUF;
        #pragma unroll
        for (int kc = 0; kc < 4; kc++) {
            #pragma unroll
            for (int nfp = 0; nfp < 4; nfp++) {
                unsigned kq[4];
                ldsm_x4(kq, kbufAddr + (uint32_t)nfp * (16 * AKROW) + (uint32_t)kc * 32);
                mma_bf16(s[2 * nfp],     qf[kc], &kq[0]);
                mma_bf16(s[2 * nfp + 1], qf[kc], &kq[2]);
            }
        }

        float p[8][4];
        if (r >= 2 && r <= 7) {
            #pragma unroll
            for (int nf = 0; nf < 8; nf++) {
                p[nf][0] = ex2f(s[nf][0]);
                p[nf][1] = ex2f(s[nf][1]);
                p[nf][2] = ex2f(s[nf][2]);
                p[nf][3] = ex2f(s[nf][3]);
                d0 += p[nf][0] + p[nf][1];
                d1 += p[nf][2] + p[nf][3];
            }
        } else {
            #pragma unroll
            for (int nf = 0; nf < 8; nf++) {
                int j0  = nf * 8 + 2 * tg;
                int jr0 = 64 * r - 512 + j0;
                int jr1 = jr0 + 1;
                bool ok0 = (jr0 <= q0r)     && (jr0 >= q0r - 512);
                bool ok1 = (jr1 <= q0r)     && (jr1 >= q0r - 512);
                bool ok2 = (jr0 <= q0r + 8) && (jr0 >= q0r - 504);
                bool ok3 = (jr1 <= q0r + 8) && (jr1 >= q0r - 504);
                p[nf][0] = ok0 ? ex2f(s[nf][0]) : 0.0f;
                p[nf][1] = ok1 ? ex2f(s[nf][1]) : 0.0f;
                p[nf][2] = ok2 ? ex2f(s[nf][2]) : 0.0f;
                p[nf][3] = ok3 ? ex2f(s[nf][3]) : 0.0f;
                d0 += p[nf][0] + p[nf][1];
                d1 += p[nf][2] + p[nf][3];
            }
        }

        uint32_t vbufAddr = vAddr + (uint32_t)bi * ABUF;
        #pragma unroll
        for (int kc = 0; kc < 4; kc++) {
            unsigned a[4];
            a[0] = packbf2(p[2 * kc][0],     p[2 * kc][1]);
            a[1] = packbf2(p[2 * kc][2],     p[2 * kc][3]);
            a[2] = packbf2(p[2 * kc + 1][0], p[2 * kc + 1][1]);
            a[3] = packbf2(p[2 * kc + 1][2], p[2 * kc + 1][3]);
            #pragma unroll
            for (int nfp = 0; nfp < 4; nfp++) {
                unsigned bv[4];
                ldsm_x4_t(bv, vbufAddr + (uint32_t)kc * (16 * AKROW) + (uint32_t)nfp * 32);
                mma_bf16(o[2 * nfp],     a, &bv[0]);
                mma_bf16(o[2 * nfp + 1], a, &bv[2]);
            }
        }
    }

    d0 += __shfl_xor_sync(0xffffffffu, d0, 1);
    d0 += __shfl_xor_sync(0xffffffffu, d0, 2);
    d1 += __shfl_xor_sync(0xffffffffu, d1, 1);
    d1 += __shfl_xor_sync(0xffffffffu, d1, 2);
    float i0 = 1.0f / d0, i1 = 1.0f / d1;

    int b = bh >> 3, h = bh & 7;
    int row0 = t0 + wq * 16 + g;
    __nv_bfloat16* ob = g_o + (size_t)b * SEQ * DMODEL + h * DH;
    #pragma unroll
    for (int nf = 0; nf < 8; nf++) {
        int col = nf * 8 + 2 * tg;
        __nv_bfloat162 lo, hi;
        lo.x = __float2bfloat16(o[nf][0] * i0);
        lo.y = __float2bfloat16(o[nf][1] * i0);
        hi.x = __float2bfloat16(o[nf][2] * i1);
        hi.y = __float2bfloat16(o[nf][3] * i1);
        *(__nv_bfloat162*)&ob[(size_t)row0 * DMODEL + col]       = lo;
        *(__nv_bfloat162*)&ob[(size_t)(row0 + 8) * DMODEL + col] = hi;
    }
}

// ---------------- launch ----------------
extern "C" void kernel_launch(void* const* d_in, const int* in_sizes, int n_in,
                              void* d_out, int out_size)
{
    const float* x     = (const float*)d_in[0];
    const float* ln1g  = (const float*)d_in[1];
    const float* ln1b  = (const float*)d_in[2];
    const float* Wqkv  = (const float*)d_in[3];
    const float* qsc   = (const float*)d_in[4];
    const float* ksc   = (const float*)d_in[5];
    const float* Wout  = (const float*)d_in[6];
    const float* ln2g  = (const float*)d_in[7];
    const float* ln2b  = (const float*)d_in[8];
    const float* W1    = (const float*)d_in[9];
    const float* b1    = (const float*)d_in[10];
    const float* W2    = (const float*)d_in[11];
    const float* b2    = (const float*)d_in[12];
    float* out = (float*)d_out;

    __nv_bfloat16 *ph, *po, *pg, *pWqkvT, *pWoutT, *pW1iT, *pW2T;
    float *px1, *pb1i;
    cudaGetSymbolAddress((void**)&ph,     g_h);
    cudaGetSymbolAddress((void**)&po,     g_o);
    cudaGetSymbolAddress((void**)&px1,    g_x1);
    cudaGetSymbolAddress((void**)&pg,     g_gate);
    cudaGetSymbolAddress((void**)&pWqkvT, g_WqkvT);
    cudaGetSymbolAddress((void**)&pWoutT, g_WoutT);
    cudaGetSymbolAddress((void**)&pW1iT,  g_W1iT);
    cudaGetSymbolAddress((void**)&pW2T,   g_W2T);
    cudaGetSymbolAddress((void**)&pb1i,   g_b1i);

    cudaFuncSetAttribute(gemm_bf16<0>, cudaFuncAttributeMaxDynamicSharedMemorySize, GEMM_SMEM);
    cudaFuncSetAttribute(gemm_bf16<1>, cudaFuncAttributeMaxDynamicSharedMemorySize, GEMM_SMEM);
    cudaFuncSetAttribute(gemm_bf16<2>, cudaFuncAttributeMaxDynamicSharedMemorySize, GEMM_SMEM);
    cudaFuncSetAttribute(gemm_bf16<3>, cudaFuncAttributeMaxDynamicSharedMemorySize, GEMM_SMEM);
    cudaFuncSetAttribute(gemm_bf16<5>, cudaFuncAttributeMaxDynamicSharedMemorySize, GEMM_SMEM);
    cudaFuncSetAttribute(attn_kernel,  cudaFuncAttributeMaxDynamicSharedMemorySize, ATTN_SMEM);

    // 0) unified prep
    {
        PrepArgs pa;
        pa.Wqkv = Wqkv; pa.Wout = Wout; pa.W1 = W1; pa.W2 = W2; pa.b1 = b1;
        prep_all<<<PREP_BLOCKS, dim3(32, 8)>>>(pa);
    }

    // 1) LN1 -> h (bf16)
    ln_kernel<<<BNROWS / 8, 256>>>(x, ln1g, ln1b, ph);
    // 2) QKV GEMM + fused split/l2norm/rotary (table) -> g_q, g_k, g_v
    gemm_bf16<5><<<dim3(QKVN / 128, BNROWS / 128), 128, GEMM_SMEM>>>(
        ph, pWqkvT, qsc, ksc, nullptr, DMODEL, DMODEL, DMODEL, 0);
    // 3) local attention -> o (bf16)
    attn_kernel<<<dim3(SEQ / 128, BHEADS), 256, ATTN_SMEM>>>();
    // 4) out projection + residual -> x1 (fp32)
    gemm_bf16<1><<<dim3(DMODEL / 128, BNROWS / 128), 128, GEMM_SMEM>>>(
        po, pWoutT, nullptr, x, px1, DMODEL, DMODEL, DMODEL, DMODEL);
    // 5) LN2 -> h (bf16)
    ln_kernel<<<BNROWS / 8, 256>>>(px1, ln2g, ln2b, ph);
    // 6) FF1 + fused geglu -> gate (bf16, bounced stores)
    gemm_bf16<2><<<dim3(HID2P / 128, BNROWS / 128), 128, GEMM_SMEM>>>(
        ph, pW1iT, pb1i, nullptr, (float*)pg, DMODEL, DMODEL, DMODEL, KFF2);
    // 7) FF2 + b2 + residual -> out
    gemm_bf16<3><<<dim3(DMODEL / 128, BNROWS / 128), 128, GEMM_SMEM>>>(
        pg, pW2T, b2, px1, out, KFF2, KFF2, KFF2, DMODEL);
}